// round 7
// baseline (speedup 1.0000x reference)
#include <cuda_runtime.h>
#include <cuda_bf16.h>
#include <cuda_fp16.h>
#include <cstdint>

#define NN 50000
#define EE 800000
#define FD 128
#define ZD 64

// ---------------- scratch (device globals; no allocation allowed) ----------
__device__ __align__(256) float  g_bufA[NN * FD];
__device__ __align__(256) __half g_H16[NN * FD];
__device__ __align__(256) __nv_bfloat16 g_Bh16[128 * 512];
__device__ __align__(256) __nv_bfloat16 g_Bl16[128 * 512];
__device__ int   g_cnt[NN];
__device__ int   g_cursor[NN];
__device__ int   g_off[NN + 1];
__device__ int   g_bsum[64];
__device__ int   g_boff[64];
__device__ float g_dis[NN];
__device__ int   g_csr_src[EE];
__device__ float g_csr_norm[EE];
__device__ int   g_is64;

// ---------------- PTX helpers ----------------------------------------------
__device__ __forceinline__ uint32_t smem_u32(const void* p) {
    uint32_t a;
    asm("{ .reg .u64 t; cvta.to.shared.u64 t, %1; cvt.u32.u64 %0, t; }"
        : "=r"(a) : "l"(p));
    return a;
}

#define LDSM_X4(r0, r1, r2, r3, addr) \
    asm volatile("ldmatrix.sync.aligned.m8n8.x4.shared.b16 {%0,%1,%2,%3}, [%4];" \
        : "=r"(r0), "=r"(r1), "=r"(r2), "=r"(r3) : "r"(addr))

#define MMA_BF16(d, a, b0, b1) \
    asm volatile("mma.sync.aligned.m16n8k16.row.col.f32.bf16.bf16.f32 " \
        "{%0,%1,%2,%3}, {%4,%5,%6,%7}, {%8,%9}, {%0,%1,%2,%3};" \
        : "+f"((d)[0]), "+f"((d)[1]), "+f"((d)[2]), "+f"((d)[3]) \
        : "r"((a)[0]), "r"((a)[1]), "r"((a)[2]), "r"((a)[3]), "r"(b0), "r"(b1))

// ---------------- preprocessing --------------------------------------------
__device__ __forceinline__ int edge_at(const void* eiv, long idx) {
    if (g_is64) return (int)((const long long*)eiv)[idx];
    return ((const int*)eiv)[idx];
}

// zero counts + detect edge dtype (block 0, warp 0)
__global__ void k_init(const int* __restrict__ ei32) {
    int i = blockIdx.x * blockDim.x + threadIdx.x;
    if (i < NN) g_cnt[i] = 0;
    if (blockIdx.x == 0 && threadIdx.x < 32) {
        int v = ei32[2 * threadIdx.x + 1];
        unsigned m = __ballot_sync(0xffffffffu, v != 0);
        if (threadIdx.x == 0) g_is64 = (m == 0) ? 1 : 0;
    }
}

__global__ void k_count(const void* __restrict__ eiv) {
    int e = blockIdx.x * blockDim.x + threadIdx.x;
    if (e < EE) {
        int d = edge_at(eiv, (long)EE + e);
        atomicAdd(&g_cnt[d], 1);
    }
}

// exclusive scan of g_cnt into g_off; also writes g_dis = rsqrt(deg+1)
__global__ void k_scan1() {
    __shared__ int ws[32];
    int i = blockIdx.x * 1024 + threadIdx.x;
    int lane = threadIdx.x & 31, wid = threadIdx.x >> 5;
    int v = (i < NN) ? g_cnt[i] : 0;
    int orig = v;
    if (i < NN) g_dis[i] = rsqrtf((float)(orig + 1));
#pragma unroll
    for (int d = 1; d < 32; d <<= 1) {
        int n = __shfl_up_sync(0xffffffffu, v, d);
        if (lane >= d) v += n;
    }
    if (lane == 31) ws[wid] = v;
    __syncthreads();
    if (wid == 0) {
        int s = ws[lane];
#pragma unroll
        for (int d = 1; d < 32; d <<= 1) {
            int n = __shfl_up_sync(0xffffffffu, s, d);
            if (lane >= d) s += n;
        }
        ws[lane] = s;
    }
    __syncthreads();
    int incl = v + (wid > 0 ? ws[wid - 1] : 0);
    if (i < NN) g_off[i] = incl - orig;
    if (threadIdx.x == 1023) g_bsum[blockIdx.x] = incl;
}

__global__ void k_scan2(int nblk) {
    __shared__ int w0sum;
    int t = threadIdx.x, lane = t & 31, wid = t >> 5;
    int v = (t < nblk) ? g_bsum[t] : 0;
    int orig = v;
#pragma unroll
    for (int d = 1; d < 32; d <<= 1) {
        int n = __shfl_up_sync(0xffffffffu, v, d);
        if (lane >= d) v += n;
    }
    if (wid == 0 && lane == 31) w0sum = v;
    __syncthreads();
    int incl = v + (wid == 1 ? w0sum : 0);
    if (t < nblk) g_boff[t] = incl - orig;
}

__global__ void k_scan3() {
    int i = blockIdx.x * blockDim.x + threadIdx.x;
    if (i < NN) {
        g_off[i] += g_boff[i >> 10];
        g_cursor[i] = 0;
    }
    if (i == 0) g_off[NN] = EE;
}

__global__ void k_fill(const void* __restrict__ eiv) {
    int e = blockIdx.x * blockDim.x + threadIdx.x;
    if (e < EE) {
        int s = edge_at(eiv, e);
        int d = edge_at(eiv, (long)EE + e);
        int pos = g_off[d] + atomicAdd(&g_cursor[d], 1);
        g_csr_src[pos]  = s;
        g_csr_norm[pos] = g_dis[s] * g_dis[d];
    }
}

// ---------------- W prep: split to bf16 hi/lo, transpose to [N=128][K] -----
__global__ void k_prepB(const float* __restrict__ Wa, const float* __restrict__ Wb,
                        int K, int split) {
    int i = blockIdx.x * blockDim.x + threadIdx.x;
    if (i >= 128 * K) return;
    int n = i / K, k = i - n * K;
    float v;
    if (split) v = (n < 64) ? Wa[k * 64 + n] : Wb[k * 64 + (n - 64)];
    else       v = Wa[k * 128 + n];
    __nv_bfloat16 h = __float2bfloat16_rn(v);
    __nv_bfloat16 l = __float2bfloat16_rn(v - __bfloat162float(h));
    g_Bh16[i] = h;
    g_Bl16[i] = l;
}

// ---------------- bf16 split-3 tensor-core GEMM, fp16 output ---------------
// C_fp16[M x 128] = A[M x K] @ B[K x 128]; 128x128 CTA tile, 8 warps of 32x64.
static constexpr int ROWB   = 80;                 // padded bf16 row (conflict-free ldmatrix)
static constexpr int AHALF  = 128 * ROWB;         // 10240
static constexpr int STAGE  = 4 * AHALF;          // Ah | Al | Bh | Bl
static constexpr int GEMM_SMEM = 2 * STAGE;       // 81920

template <int K>
__global__ __launch_bounds__(256) void k_tgemm(
    const float* __restrict__ A, __half* __restrict__ C)
{
    extern __shared__ __align__(256) char smem[];
    constexpr int NCH = K / 32;
    const int tid  = threadIdx.x;
    const int wid  = tid >> 5;
    const int lane = tid & 31;
    const int warp_m = wid & 3;
    const int warp_n = wid >> 2;
    const uint32_t sb = smem_u32(smem);
    const int rowBase = blockIdx.x * 128;

    const uint32_t a_off = (uint32_t)(((lane & 7) + ((lane >> 3) & 1) * 8) * ROWB
                                      + ((lane >> 4) & 1) * 16);
    const uint32_t b_off = (uint32_t)((((lane >> 4) & 1) * 8 + (lane & 7)) * ROWB
                                      + ((lane >> 3) & 1) * 16);

    float acc[2][8][4];
#pragma unroll
    for (int t = 0; t < 2; t++)
#pragma unroll
        for (int j = 0; j < 8; j++)
#pragma unroll
            for (int v = 0; v < 4; v++) acc[t][j][v] = 0.f;

    const int ar = tid >> 1;
    const int aq = (tid & 1) * 4;
    const int br = tid >> 1;
    const int bq = (tid & 1) << 1;

    auto sts_chunk = [&](int s, const float4* pa, const uint4* pbh, const uint4* pbl) {
        char* st = smem + s * STAGE;
#pragma unroll
        for (int it = 0; it < 4; it++) {
            int q = aq + it;
            float4 v = pa[it];
            __nv_bfloat162 h01 = __floats2bfloat162_rn(v.x, v.y);
            __nv_bfloat162 h23 = __floats2bfloat162_rn(v.z, v.w);
            float2 hf0 = __bfloat1622float2(h01);
            float2 hf1 = __bfloat1622float2(h23);
            __nv_bfloat162 l01 = __floats2bfloat162_rn(v.x - hf0.x, v.y - hf0.y);
            __nv_bfloat162 l23 = __floats2bfloat162_rn(v.z - hf1.x, v.w - hf1.y);
            uint32_t off = (uint32_t)(ar * ROWB + q * 8);
            *reinterpret_cast<__nv_bfloat162*>(st + off)             = h01;
            *reinterpret_cast<__nv_bfloat162*>(st + off + 4)         = h23;
            *reinterpret_cast<__nv_bfloat162*>(st + AHALF + off)     = l01;
            *reinterpret_cast<__nv_bfloat162*>(st + AHALF + off + 4) = l23;
        }
#pragma unroll
        for (int it = 0; it < 2; it++) {
            int q = bq + it;
            uint32_t off = (uint32_t)(br * ROWB + q * 16);
            *reinterpret_cast<uint4*>(st + 2 * AHALF + off) = pbh[it];
            *reinterpret_cast<uint4*>(st + 3 * AHALF + off) = pbl[it];
        }
    };

    auto ldg_chunk = [&](int c, float4* pa, uint4* pbh, uint4* pbl) {
#pragma unroll
        for (int it = 0; it < 4; it++) {
            int q = aq + it;
            int row = rowBase + ar;
            float4 v = make_float4(0.f, 0.f, 0.f, 0.f);
            if (row < NN)
                v = *reinterpret_cast<const float4*>(&A[(size_t)row * K + c * 32 + q * 4]);
            pa[it] = v;
        }
#pragma unroll
        for (int it = 0; it < 2; it++) {
            int q = bq + it;
            size_t idx = (size_t)br * K + c * 32 + q * 8;
            pbh[it] = *reinterpret_cast<const uint4*>(&g_Bh16[idx]);
            pbl[it] = *reinterpret_cast<const uint4*>(&g_Bl16[idx]);
        }
    };

    {
        float4 pa[4]; uint4 pbh[2], pbl[2];
        ldg_chunk(0, pa, pbh, pbl);
        sts_chunk(0, pa, pbh, pbl);
    }
    __syncthreads();

    for (int c = 0; c < NCH; c++) {
        const int s = c & 1;
        float4 pa[4]; uint4 pbh[2], pbl[2];
        if (c + 1 < NCH) ldg_chunk(c + 1, pa, pbh, pbl);

        const uint32_t aBaseH = sb + s * STAGE + (uint32_t)(warp_m * 32) * ROWB;
        const uint32_t bBaseH = sb + s * STAGE + 2 * AHALF + (uint32_t)(warp_n * 64) * ROWB;

#pragma unroll
        for (int sk = 0; sk < 2; sk++) {
            uint32_t ah[2][4], al[2][4];
#pragma unroll
            for (int t = 0; t < 2; t++) {
                uint32_t ad = aBaseH + (uint32_t)(t * 16 * ROWB + sk * 32) + a_off;
                LDSM_X4(ah[t][0], ah[t][1], ah[t][2], ah[t][3], ad);
                LDSM_X4(al[t][0], al[t][1], al[t][2], al[t][3], ad + AHALF);
            }
            uint32_t bh[4][4], bl[4][4];
#pragma unroll
            for (int jp = 0; jp < 4; jp++) {
                uint32_t bd = bBaseH + (uint32_t)(jp * 16 * ROWB + sk * 32) + b_off;
                LDSM_X4(bh[jp][0], bh[jp][1], bh[jp][2], bh[jp][3], bd);
                LDSM_X4(bl[jp][0], bl[jp][1], bl[jp][2], bl[jp][3], bd + AHALF);
            }
#pragma unroll
            for (int t = 0; t < 2; t++)
#pragma unroll
                for (int j = 0; j < 8; j++) {
                    int jp = j >> 1, o = (j & 1) * 2;
                    MMA_BF16(acc[t][j], ah[t], bh[jp][o], bh[jp][o + 1]);
                    MMA_BF16(acc[t][j], ah[t], bl[jp][o], bl[jp][o + 1]);
                    MMA_BF16(acc[t][j], al[t], bh[jp][o], bh[jp][o + 1]);
                }
        }

        if (c + 1 < NCH) sts_chunk(s ^ 1, pa, pbh, pbl);
        __syncthreads();
    }

    // epilogue: fp16 stores
    const int r0 = rowBase + warp_m * 32 + (lane >> 2);
    const int cb = (lane & 3) * 2;
#pragma unroll
    for (int t = 0; t < 2; t++) {
#pragma unroll
        for (int j = 0; j < 8; j++) {
            int col = warp_n * 64 + j * 8 + cb;
            int ra = r0 + t * 16;
            int rb = ra + 8;
            if (ra < NN)
                *reinterpret_cast<__half2*>(&C[(size_t)ra * 128 + col]) =
                    __floats2half2_rn(acc[t][j][0], acc[t][j][1]);
            if (rb < NN)
                *reinterpret_cast<__half2*>(&C[(size_t)rb * 128 + col]) =
                    __floats2half2_rn(acc[t][j][2], acc[t][j][3]);
        }
    }
}

// ---------------- aggregation (fp16 gathers, fp32 accumulate) --------------
// MODE 1: O = relu(sum + biasA), fp32 [node][128]
// MODE 2: cols 0-63 -> OA + biasA, cols 64-127 -> OB + biasB (fp32 [node][64])
template <int MODE>
__global__ __launch_bounds__(256) void k_agg(
    const uint2* __restrict__ G,   // fp16 table: [node][32] x 8B
    const float* __restrict__ biasA, const float* __restrict__ biasB,
    float* __restrict__ OA, float* __restrict__ OB)
{
    int node = (blockIdx.x * blockDim.x + threadIdx.x) >> 5;
    int lane = threadIdx.x & 31;
    if (node >= NN) return;
    int e0 = g_off[node], e1 = g_off[node + 1];
    float dii = g_dis[node];
    float w0 = dii * dii;
    uint2 r = G[(size_t)node * 32 + lane];
    float2 p0 = __half22float2(*reinterpret_cast<__half2*>(&r.x));
    float2 p1 = __half22float2(*reinterpret_cast<__half2*>(&r.y));
    float4 acc = make_float4(w0 * p0.x, w0 * p0.y, w0 * p1.x, w0 * p1.y);
#pragma unroll 4
    for (int e = e0; e < e1; e++) {
        int   s = g_csr_src[e];        // warp-broadcast
        float w = g_csr_norm[e];
        uint2 m = G[(size_t)s * 32 + lane];
        float2 q0 = __half22float2(*reinterpret_cast<__half2*>(&m.x));
        float2 q1 = __half22float2(*reinterpret_cast<__half2*>(&m.y));
        acc.x = fmaf(w, q0.x, acc.x);
        acc.y = fmaf(w, q0.y, acc.y);
        acc.z = fmaf(w, q1.x, acc.z);
        acc.w = fmaf(w, q1.y, acc.w);
    }
    if (MODE == 1) {
        float4 b = reinterpret_cast<const float4*>(biasA)[lane];
        acc.x = fmaxf(acc.x + b.x, 0.f);
        acc.y = fmaxf(acc.y + b.y, 0.f);
        acc.z = fmaxf(acc.z + b.z, 0.f);
        acc.w = fmaxf(acc.w + b.w, 0.f);
        reinterpret_cast<float4*>(OA)[(size_t)node * 32 + lane] = acc;
    } else {
        if (lane < 16) {
            float4 b = reinterpret_cast<const float4*>(biasA)[lane];
            acc.x += b.x; acc.y += b.y; acc.z += b.z; acc.w += b.w;
            reinterpret_cast<float4*>(OA)[(size_t)node * 16 + lane] = acc;
        } else {
            float4 b = reinterpret_cast<const float4*>(biasB)[lane - 16];
            acc.x += b.x; acc.y += b.y; acc.z += b.z; acc.w += b.w;
            reinterpret_cast<float4*>(OB)[(size_t)node * 16 + (lane - 16)] = acc;
        }
    }
}

// ---------------- launch ----------------------------------------------------
extern "C" void kernel_launch(void* const* d_in, const int* in_sizes, int n_in,
                              void* d_out, int out_size) {
    const float* x  = (const float*)d_in[0];
    const void*  ei = d_in[1];
    const float* W1 = (const float*)d_in[2];
    const float* b1 = (const float*)d_in[3];
    const float* W2 = (const float*)d_in[4];
    const float* b2 = (const float*)d_in[5];
    const float* Wm = (const float*)d_in[6];
    const float* bm = (const float*)d_in[7];
    const float* Ws = (const float*)d_in[8];
    const float* bs = (const float*)d_in[9];
    float* outM = (float*)d_out;
    float* outS = outM + (long)NN * ZD;

    float*  pA = nullptr;
    __half* pH = nullptr;
    cudaGetSymbolAddress((void**)&pA, g_bufA);
    cudaGetSymbolAddress((void**)&pH, g_H16);

    cudaFuncSetAttribute(k_tgemm<512>, cudaFuncAttributeMaxDynamicSharedMemorySize, GEMM_SMEM);
    cudaFuncSetAttribute(k_tgemm<128>, cudaFuncAttributeMaxDynamicSharedMemorySize, GEMM_SMEM);

    const int T = 256;
    const int nblk_scan = (NN + 1023) / 1024;

    // preprocessing: CSR by dst + sym-norm weights
    k_init<<<(NN + T - 1) / T, T>>>((const int*)ei);
    k_count<<<(EE + T - 1) / T, T>>>(ei);
    k_scan1<<<nblk_scan, 1024>>>();
    k_scan2<<<1, 64>>>(nblk_scan);
    k_scan3<<<(NN + T - 1) / T, T>>>();
    k_fill<<<(EE + T - 1) / T, T>>>(ei);

    const int gb = (NN + 127) / 128;           // 391 CTAs
    const int ab = (NN * 32 + T - 1) / T;      // agg blocks

    // layer 1: H16 = fp16(x @ W1) ; h1 = relu(A H16 + b1)
    k_prepB<<<(128 * 512 + T - 1) / T, T>>>(W1, nullptr, 512, 0);
    k_tgemm<512><<<gb, 256, GEMM_SMEM>>>(x, pH);
    k_agg<1><<<ab, T>>>((const uint2*)pH, b1, nullptr, pA, nullptr);
    // layer 2: H16 = fp16(h1 @ W2) ; h2 = relu(A H16 + b2)
    k_prepB<<<(128 * 128 + T - 1) / T, T>>>(W2, nullptr, 128, 0);
    k_tgemm<128><<<gb, 256, GEMM_SMEM>>>(pA, pH);
    k_agg<1><<<ab, T>>>((const uint2*)pH, b2, nullptr, pA, nullptr);
    // heads: H16 = fp16(h2 @ [Wm|Ws]) ; [z_mean|z_log_std] = A H16 + [bm|bs]
    k_prepB<<<(128 * 128 + T - 1) / T, T>>>(Wm, Ws, 128, 1);
    k_tgemm<128><<<gb, 256, GEMM_SMEM>>>(pA, pH);
    k_agg<2><<<ab, T>>>((const uint2*)pH, bm, bs, outM, outS);
}

// round 8
// speedup vs baseline: 1.0922x; 1.0922x over previous
#include <cuda_runtime.h>
#include <cuda_bf16.h>
#include <cuda_fp16.h>
#include <cstdint>

#define NN 50000
#define EE 800000
#define FD 128
#define ZD 64
#define CAP 128          // bucket capacity per node (Poisson(16); overflow ~1e-18)

// ---------------- scratch (device globals; no allocation allowed) ----------
__device__ __align__(256) float  g_bufA[NN * FD];
__device__ __align__(256) __half g_H16[NN * FD];
__device__ __align__(256) __nv_bfloat16 g_Bh16[128 * 512 + 2 * 128 * 128];
__device__ __align__(256) __nv_bfloat16 g_Bl16[128 * 512 + 2 * 128 * 128];
__device__ __align__(256) int    g_src[NN * CAP];
__device__ int   g_cnt[NN];
__device__ float g_dis[NN];
__device__ int   g_is64;

// ---------------- PTX helpers ----------------------------------------------
__device__ __forceinline__ uint32_t smem_u32(const void* p) {
    uint32_t a;
    asm("{ .reg .u64 t; cvta.to.shared.u64 t, %1; cvt.u32.u64 %0, t; }"
        : "=r"(a) : "l"(p));
    return a;
}

#define LDSM_X4(r0, r1, r2, r3, addr) \
    asm volatile("ldmatrix.sync.aligned.m8n8.x4.shared.b16 {%0,%1,%2,%3}, [%4];" \
        : "=r"(r0), "=r"(r1), "=r"(r2), "=r"(r3) : "r"(addr))

#define MMA_BF16(d, a, b0, b1) \
    asm volatile("mma.sync.aligned.m16n8k16.row.col.f32.bf16.bf16.f32 " \
        "{%0,%1,%2,%3}, {%4,%5,%6,%7}, {%8,%9}, {%0,%1,%2,%3};" \
        : "+f"((d)[0]), "+f"((d)[1]), "+f"((d)[2]), "+f"((d)[3]) \
        : "r"((a)[0]), "r"((a)[1]), "r"((a)[2]), "r"((a)[3]), "r"(b0), "r"(b1))

// ---------------- preprocessing --------------------------------------------
__device__ __forceinline__ int edge_at(const void* eiv, long idx) {
    if (g_is64) return (int)((const long long*)eiv)[idx];
    return ((const int*)eiv)[idx];
}

// zero counts + detect edge dtype (block 0, warp 0)
__global__ void k_init(const int* __restrict__ ei32) {
    int i = blockIdx.x * blockDim.x + threadIdx.x;
    if (i < NN) g_cnt[i] = 0;
    if (blockIdx.x == 0 && threadIdx.x < 32) {
        int v = ei32[2 * threadIdx.x + 1];
        unsigned m = __ballot_sync(0xffffffffu, v != 0);
        if (threadIdx.x == 0) g_is64 = (m == 0) ? 1 : 0;
    }
}

// single-pass bucket CSR: count + scatter src
__global__ void k_fillcnt(const void* __restrict__ eiv) {
    int e = blockIdx.x * blockDim.x + threadIdx.x;
    if (e < EE) {
        int s = edge_at(eiv, e);
        int d = edge_at(eiv, (long)EE + e);
        int pos = atomicAdd(&g_cnt[d], 1);
        if (pos < CAP) g_src[(d << 7) + pos] = s;
    }
}

// weights prep (split to bf16 hi/lo, transpose to [N=128][K]) + dis = rsqrt(deg+1)
// region 0: W1 (128x512) at offset 0; region 1: W2 (128x128) at 65536;
// region 2: [Wm|Ws] (128x128) at 81920. Total 98304 threads.
__global__ void k_prep2(const float* __restrict__ W1, const float* __restrict__ W2,
                        const float* __restrict__ Wm, const float* __restrict__ Ws) {
    int i = blockIdx.x * blockDim.x + threadIdx.x;
    if (i < NN) g_dis[i] = rsqrtf((float)(g_cnt[i] + 1));
    if (i >= 98304) return;
    float v;
    if (i < 65536) {
        int n = i >> 9, k = i & 511;
        v = W1[k * 128 + n];
    } else if (i < 81920) {
        int idx = i - 65536;
        int n = idx >> 7, k = idx & 127;
        v = W2[k * 128 + n];
    } else {
        int idx = i - 81920;
        int n = idx >> 7, k = idx & 127;
        v = (n < 64) ? Wm[k * 64 + n] : Ws[k * 64 + (n - 64)];
    }
    __nv_bfloat16 h = __float2bfloat16_rn(v);
    __nv_bfloat16 l = __float2bfloat16_rn(v - __bfloat162float(h));
    g_Bh16[i] = h;
    g_Bl16[i] = l;
}

// ---------------- bf16 split-3 tensor-core GEMM, fp16 output ---------------
// C_fp16[M x 128] = A[M x K] @ B[K x 128]; 128x128 CTA tile, 8 warps of 32x64.
static constexpr int ROWB   = 80;                 // padded bf16 row (conflict-free ldmatrix)
static constexpr int AHALF  = 128 * ROWB;         // 10240
static constexpr int STAGE  = 4 * AHALF;          // Ah | Al | Bh | Bl
static constexpr int GEMM_SMEM = 2 * STAGE;       // 81920

template <int K>
__global__ __launch_bounds__(256) void k_tgemm(
    const float* __restrict__ A,
    const __nv_bfloat16* __restrict__ Bh, const __nv_bfloat16* __restrict__ Bl,
    __half* __restrict__ C)
{
    extern __shared__ __align__(256) char smem[];
    constexpr int NCH = K / 32;
    const int tid  = threadIdx.x;
    const int wid  = tid >> 5;
    const int lane = tid & 31;
    const int warp_m = wid & 3;
    const int warp_n = wid >> 2;
    const uint32_t sb = smem_u32(smem);
    const int rowBase = blockIdx.x * 128;

    const uint32_t a_off = (uint32_t)(((lane & 7) + ((lane >> 3) & 1) * 8) * ROWB
                                      + ((lane >> 4) & 1) * 16);
    const uint32_t b_off = (uint32_t)((((lane >> 4) & 1) * 8 + (lane & 7)) * ROWB
                                      + ((lane >> 3) & 1) * 16);

    float acc[2][8][4];
#pragma unroll
    for (int t = 0; t < 2; t++)
#pragma unroll
        for (int j = 0; j < 8; j++)
#pragma unroll
            for (int v = 0; v < 4; v++) acc[t][j][v] = 0.f;

    const int ar = tid >> 1;
    const int aq = (tid & 1) * 4;
    const int br = tid >> 1;
    const int bq = (tid & 1) << 1;

    auto sts_chunk = [&](int s, const float4* pa, const uint4* pbh, const uint4* pbl) {
        char* st = smem + s * STAGE;
#pragma unroll
        for (int it = 0; it < 4; it++) {
            int q = aq + it;
            float4 v = pa[it];
            __nv_bfloat162 h01 = __floats2bfloat162_rn(v.x, v.y);
            __nv_bfloat162 h23 = __floats2bfloat162_rn(v.z, v.w);
            float2 hf0 = __bfloat1622float2(h01);
            float2 hf1 = __bfloat1622float2(h23);
            __nv_bfloat162 l01 = __floats2bfloat162_rn(v.x - hf0.x, v.y - hf0.y);
            __nv_bfloat162 l23 = __floats2bfloat162_rn(v.z - hf1.x, v.w - hf1.y);
            uint32_t off = (uint32_t)(ar * ROWB + q * 8);
            *reinterpret_cast<__nv_bfloat162*>(st + off)             = h01;
            *reinterpret_cast<__nv_bfloat162*>(st + off + 4)         = h23;
            *reinterpret_cast<__nv_bfloat162*>(st + AHALF + off)     = l01;
            *reinterpret_cast<__nv_bfloat162*>(st + AHALF + off + 4) = l23;
        }
#pragma unroll
        for (int it = 0; it < 2; it++) {
            int q = bq + it;
            uint32_t off = (uint32_t)(br * ROWB + q * 16);
            *reinterpret_cast<uint4*>(st + 2 * AHALF + off) = pbh[it];
            *reinterpret_cast<uint4*>(st + 3 * AHALF + off) = pbl[it];
        }
    };

    auto ldg_chunk = [&](int c, float4* pa, uint4* pbh, uint4* pbl) {
#pragma unroll
        for (int it = 0; it < 4; it++) {
            int q = aq + it;
            int row = rowBase + ar;
            float4 v = make_float4(0.f, 0.f, 0.f, 0.f);
            if (row < NN)
                v = *reinterpret_cast<const float4*>(&A[(size_t)row * K + c * 32 + q * 4]);
            pa[it] = v;
        }
#pragma unroll
        for (int it = 0; it < 2; it++) {
            int q = bq + it;
            size_t idx = (size_t)br * K + c * 32 + q * 8;
            pbh[it] = *reinterpret_cast<const uint4*>(&Bh[idx]);
            pbl[it] = *reinterpret_cast<const uint4*>(&Bl[idx]);
        }
    };

    {
        float4 pa[4]; uint4 pbh[2], pbl[2];
        ldg_chunk(0, pa, pbh, pbl);
        sts_chunk(0, pa, pbh, pbl);
    }
    __syncthreads();

    for (int c = 0; c < NCH; c++) {
        const int s = c & 1;
        float4 pa[4]; uint4 pbh[2], pbl[2];
        if (c + 1 < NCH) ldg_chunk(c + 1, pa, pbh, pbl);

        const uint32_t aBaseH = sb + s * STAGE + (uint32_t)(warp_m * 32) * ROWB;
        const uint32_t bBaseH = sb + s * STAGE + 2 * AHALF + (uint32_t)(warp_n * 64) * ROWB;

#pragma unroll
        for (int sk = 0; sk < 2; sk++) {
            uint32_t ah[2][4], al[2][4];
#pragma unroll
            for (int t = 0; t < 2; t++) {
                uint32_t ad = aBaseH + (uint32_t)(t * 16 * ROWB + sk * 32) + a_off;
                LDSM_X4(ah[t][0], ah[t][1], ah[t][2], ah[t][3], ad);
                LDSM_X4(al[t][0], al[t][1], al[t][2], al[t][3], ad + AHALF);
            }
            uint32_t bh[4][4], bl[4][4];
#pragma unroll
            for (int jp = 0; jp < 4; jp++) {
                uint32_t bd = bBaseH + (uint32_t)(jp * 16 * ROWB + sk * 32) + b_off;
                LDSM_X4(bh[jp][0], bh[jp][1], bh[jp][2], bh[jp][3], bd);
                LDSM_X4(bl[jp][0], bl[jp][1], bl[jp][2], bl[jp][3], bd + AHALF);
            }
#pragma unroll
            for (int t = 0; t < 2; t++)
#pragma unroll
                for (int j = 0; j < 8; j++) {
                    int jp = j >> 1, o = (j & 1) * 2;
                    MMA_BF16(acc[t][j], ah[t], bh[jp][o], bh[jp][o + 1]);
                    MMA_BF16(acc[t][j], ah[t], bl[jp][o], bl[jp][o + 1]);
                    MMA_BF16(acc[t][j], al[t], bh[jp][o], bh[jp][o + 1]);
                }
        }

        if (c + 1 < NCH) sts_chunk(s ^ 1, pa, pbh, pbl);
        __syncthreads();
    }

    // epilogue: fp16 stores
    const int r0 = rowBase + warp_m * 32 + (lane >> 2);
    const int cb = (lane & 3) * 2;
#pragma unroll
    for (int t = 0; t < 2; t++) {
#pragma unroll
        for (int j = 0; j < 8; j++) {
            int col = warp_n * 64 + j * 8 + cb;
            int ra = r0 + t * 16;
            int rb = ra + 8;
            if (ra < NN)
                *reinterpret_cast<__half2*>(&C[(size_t)ra * 128 + col]) =
                    __floats2half2_rn(acc[t][j][0], acc[t][j][1]);
            if (rb < NN)
                *reinterpret_cast<__half2*>(&C[(size_t)rb * 128 + col]) =
                    __floats2half2_rn(acc[t][j][2], acc[t][j][3]);
        }
    }
}

// ---------------- aggregation (fp16 gathers, fp32 accumulate) --------------
// MODE 1: O = relu(sum + biasA), fp32 [node][128]
// MODE 2: cols 0-63 -> OA + biasA, cols 64-127 -> OB + biasB (fp32 [node][64])
template <int MODE>
__global__ __launch_bounds__(256) void k_agg(
    const uint2* __restrict__ G,   // fp16 table: [node][32] x 8B
    const float* __restrict__ biasA, const float* __restrict__ biasB,
    float* __restrict__ OA, float* __restrict__ OB)
{
    int node = (blockIdx.x * blockDim.x + threadIdx.x) >> 5;
    int lane = threadIdx.x & 31;
    if (node >= NN) return;
    int n = g_cnt[node];
    n = (n < CAP) ? n : CAP;
    const int base = node << 7;
    float dd = g_dis[node];
    float w0 = dd * dd;
    uint2 r = G[(size_t)node * 32 + lane];
    float2 p0 = __half22float2(*reinterpret_cast<__half2*>(&r.x));
    float2 p1 = __half22float2(*reinterpret_cast<__half2*>(&r.y));
    float4 acc = make_float4(w0 * p0.x, w0 * p0.y, w0 * p1.x, w0 * p1.y);
#pragma unroll 4
    for (int j = 0; j < n; j++) {
        int   s = g_src[base + j];           // warp-broadcast
        float w = g_dis[s] * dd;             // warp-broadcast
        uint2 m = G[(size_t)s * 32 + lane];
        float2 q0 = __half22float2(*reinterpret_cast<__half2*>(&m.x));
        float2 q1 = __half22float2(*reinterpret_cast<__half2*>(&m.y));
        acc.x = fmaf(w, q0.x, acc.x);
        acc.y = fmaf(w, q0.y, acc.y);
        acc.z = fmaf(w, q1.x, acc.z);
        acc.w = fmaf(w, q1.y, acc.w);
    }
    if (MODE == 1) {
        float4 b = reinterpret_cast<const float4*>(biasA)[lane];
        acc.x = fmaxf(acc.x + b.x, 0.f);
        acc.y = fmaxf(acc.y + b.y, 0.f);
        acc.z = fmaxf(acc.z + b.z, 0.f);
        acc.w = fmaxf(acc.w + b.w, 0.f);
        reinterpret_cast<float4*>(OA)[(size_t)node * 32 + lane] = acc;
    } else {
        if (lane < 16) {
            float4 b = reinterpret_cast<const float4*>(biasA)[lane];
            acc.x += b.x; acc.y += b.y; acc.z += b.z; acc.w += b.w;
            reinterpret_cast<float4*>(OA)[(size_t)node * 16 + lane] = acc;
        } else {
            float4 b = reinterpret_cast<const float4*>(biasB)[lane - 16];
            acc.x += b.x; acc.y += b.y; acc.z += b.z; acc.w += b.w;
            reinterpret_cast<float4*>(OB)[(size_t)node * 16 + (lane - 16)] = acc;
        }
    }
}

// ---------------- launch ----------------------------------------------------
extern "C" void kernel_launch(void* const* d_in, const int* in_sizes, int n_in,
                              void* d_out, int out_size) {
    const float* x  = (const float*)d_in[0];
    const void*  ei = d_in[1];
    const float* W1 = (const float*)d_in[2];
    const float* b1 = (const float*)d_in[3];
    const float* W2 = (const float*)d_in[4];
    const float* b2 = (const float*)d_in[5];
    const float* Wm = (const float*)d_in[6];
    const float* bm = (const float*)d_in[7];
    const float* Ws = (const float*)d_in[8];
    const float* bs = (const float*)d_in[9];
    float* outM = (float*)d_out;
    float* outS = outM + (long)NN * ZD;

    float*  pA  = nullptr;
    __half* pH  = nullptr;
    __nv_bfloat16 *pBh = nullptr, *pBl = nullptr;
    cudaGetSymbolAddress((void**)&pA,  g_bufA);
    cudaGetSymbolAddress((void**)&pH,  g_H16);
    cudaGetSymbolAddress((void**)&pBh, g_Bh16);
    cudaGetSymbolAddress((void**)&pBl, g_Bl16);

    cudaFuncSetAttribute(k_tgemm<512>, cudaFuncAttributeMaxDynamicSharedMemorySize, GEMM_SMEM);
    cudaFuncSetAttribute(k_tgemm<128>, cudaFuncAttributeMaxDynamicSharedMemorySize, GEMM_SMEM);

    const int T = 256;
    const int gb = (NN + 127) / 128;           // 391 CTAs
    const int ab = (NN * 32 + T - 1) / T;      // agg blocks

    // preprocessing: bucket CSR + weights + dis (3 launches)
    k_init<<<(NN + T - 1) / T, T>>>((const int*)ei);
    k_fillcnt<<<(EE + T - 1) / T, T>>>(ei);
    k_prep2<<<384, 256>>>(W1, W2, Wm, Ws);

    // layer 1: H16 = fp16(x @ W1) ; h1 = relu(A H16 + b1)
    k_tgemm<512><<<gb, 256, GEMM_SMEM>>>(x, pBh, pBl, pH);
    k_agg<1><<<ab, T>>>((const uint2*)pH, b1, nullptr, pA, nullptr);
    // layer 2: H16 = fp16(h1 @ W2) ; h2 = relu(A H16 + b2)
    k_tgemm<128><<<gb, 256, GEMM_SMEM>>>(pA, pBh + 65536, pBl + 65536, pH);
    k_agg<1><<<ab, T>>>((const uint2*)pH, b2, nullptr, pA, nullptr);
    // heads: H16 = fp16(h2 @ [Wm|Ws]) ; [z_mean|z_log_std] = A H16 + [bm|bs]
    k_tgemm<128><<<gb, 256, GEMM_SMEM>>>(pA, pBh + 81920, pBl + 81920, pH);
    k_agg<2><<<ab, T>>>((const uint2*)pH, bm, bs, outM, outS);
}

// round 9
// speedup vs baseline: 1.1969x; 1.0958x over previous
#include <cuda_runtime.h>
#include <cuda_bf16.h>
#include <cuda_fp16.h>
#include <cstdint>

#define NN 50000
#define EE 800000
#define FD 128
#define ZD 64
#define CAP 128          // bucket capacity per node (Poisson(16); overflow ~1e-18)

// ---------------- scratch (device globals; no allocation allowed) ----------
__device__ __align__(256) float  g_bufA[NN * FD];
__device__ __align__(256) __half g_H16[NN * FD];
__device__ __align__(256) __nv_bfloat16 g_Bh16[128 * 512 + 2 * 128 * 128];
__device__ __align__(256) __nv_bfloat16 g_Bl16[128 * 512 + 2 * 128 * 128];
__device__ __align__(256) int    g_src[NN * CAP];
__device__ int   g_cnt[NN];
__device__ float g_dis[NN];
__device__ int   g_is64;

// ---------------- PTX helpers ----------------------------------------------
__device__ __forceinline__ uint32_t smem_u32(const void* p) {
    uint32_t a;
    asm("{ .reg .u64 t; cvta.to.shared.u64 t, %1; cvt.u32.u64 %0, t; }"
        : "=r"(a) : "l"(p));
    return a;
}

__device__ __forceinline__ void cp_async16(uint32_t dst, const void* src) {
    asm volatile("cp.async.ca.shared.global [%0], [%1], 16;"
                 :: "r"(dst), "l"(src));
}
#define CP_COMMIT() asm volatile("cp.async.commit_group;")
#define CP_WAIT0()  asm volatile("cp.async.wait_group 0;" ::: "memory")

#define LDSM_X4(r0, r1, r2, r3, addr) \
    asm volatile("ldmatrix.sync.aligned.m8n8.x4.shared.b16 {%0,%1,%2,%3}, [%4];" \
        : "=r"(r0), "=r"(r1), "=r"(r2), "=r"(r3) : "r"(addr))

#define MMA_BF16(d, a, b0, b1) \
    asm volatile("mma.sync.aligned.m16n8k16.row.col.f32.bf16.bf16.f32 " \
        "{%0,%1,%2,%3}, {%4,%5,%6,%7}, {%8,%9}, {%0,%1,%2,%3};" \
        : "+f"((d)[0]), "+f"((d)[1]), "+f"((d)[2]), "+f"((d)[3]) \
        : "r"((a)[0]), "r"((a)[1]), "r"((a)[2]), "r"((a)[3]), "r"(b0), "r"(b1))

// ---------------- preprocessing --------------------------------------------
__device__ __forceinline__ int edge_at(const void* eiv, long idx) {
    if (g_is64) return (int)((const long long*)eiv)[idx];
    return ((const int*)eiv)[idx];
}

// zero counts + detect edge dtype (block 0, warp 0)
__global__ void k_init(const int* __restrict__ ei32) {
    int i = blockIdx.x * blockDim.x + threadIdx.x;
    if (i < NN) g_cnt[i] = 0;
    if (blockIdx.x == 0 && threadIdx.x < 32) {
        int v = ei32[2 * threadIdx.x + 1];
        unsigned m = __ballot_sync(0xffffffffu, v != 0);
        if (threadIdx.x == 0) g_is64 = (m == 0) ? 1 : 0;
    }
}

// single-pass bucket CSR: count + scatter src
__global__ void k_fillcnt(const void* __restrict__ eiv) {
    int e = blockIdx.x * blockDim.x + threadIdx.x;
    if (e < EE) {
        int s = edge_at(eiv, e);
        int d = edge_at(eiv, (long)EE + e);
        int pos = atomicAdd(&g_cnt[d], 1);
        if (pos < CAP) g_src[(d << 7) + pos] = s;
    }
}

// weights prep (split to bf16 hi/lo, transpose to [N=128][K]) + dis = rsqrt(deg+1)
__global__ void k_prep2(const float* __restrict__ W1, const float* __restrict__ W2,
                        const float* __restrict__ Wm, const float* __restrict__ Ws) {
    int i = blockIdx.x * blockDim.x + threadIdx.x;
    if (i < NN) g_dis[i] = rsqrtf((float)(g_cnt[i] + 1));
    if (i >= 98304) return;
    float v;
    if (i < 65536) {
        int n = i >> 9, k = i & 511;
        v = W1[k * 128 + n];
    } else if (i < 81920) {
        int idx = i - 65536;
        int n = idx >> 7, k = idx & 127;
        v = W2[k * 128 + n];
    } else {
        int idx = i - 81920;
        int n = idx >> 7, k = idx & 127;
        v = (n < 64) ? Wm[k * 64 + n] : Ws[k * 64 + (n - 64)];
    }
    __nv_bfloat16 h = __float2bfloat16_rn(v);
    __nv_bfloat16 l = __float2bfloat16_rn(v - __bfloat162float(h));
    g_Bh16[i] = h;
    g_Bl16[i] = l;
}

// ---------------- bf16 split-3 tensor-core GEMM, fp16 output ---------------
// C_fp16[M x 128] = A[M x K] @ B[K x 128]; 128x128 CTA tile, 8 warps of 32x64.
// B arrives via cp.async (pre-split bf16 in global); A converted in-register.
static constexpr int ROWB   = 80;                 // padded bf16 row (conflict-free ldmatrix)
static constexpr int AHALF  = 128 * ROWB;         // 10240
static constexpr int STAGE  = 4 * AHALF;          // Ah | Al | Bh | Bl
static constexpr int GEMM_SMEM = 2 * STAGE;       // 81920

template <int K>
__global__ __launch_bounds__(256, 2) void k_tgemm(
    const float* __restrict__ A,
    const __nv_bfloat16* __restrict__ Bh, const __nv_bfloat16* __restrict__ Bl,
    __half* __restrict__ C)
{
    extern __shared__ __align__(256) char smem[];
    constexpr int NCH = K / 32;
    const int tid  = threadIdx.x;
    const int wid  = tid >> 5;
    const int lane = tid & 31;
    const int warp_m = wid & 3;
    const int warp_n = wid >> 2;
    const uint32_t sb = smem_u32(smem);
    const int rowBase = blockIdx.x * 128;

    const uint32_t a_off = (uint32_t)(((lane & 7) + ((lane >> 3) & 1) * 8) * ROWB
                                      + ((lane >> 4) & 1) * 16);
    const uint32_t b_off = (uint32_t)((((lane >> 4) & 1) * 8 + (lane & 7)) * ROWB
                                      + ((lane >> 3) & 1) * 16);

    float acc[2][8][4];
#pragma unroll
    for (int t = 0; t < 2; t++)
#pragma unroll
        for (int j = 0; j < 8; j++)
#pragma unroll
            for (int v = 0; v < 4; v++) acc[t][j][v] = 0.f;

    const int ar = tid >> 1;          // A: 128 rows, 2 thr/row
    const int aq = (tid & 1) * 4;     // A: quad base; 4 iters -> quads 0..7
    const int br = tid >> 1;          // B: 128 rows
    const int bq = (tid & 1) << 1;    // B: 16B chunk base; 2 iters -> 0..3

    // issue cp.async for B chunk c into stage s
    auto cpB = [&](int c, int s) {
        uint32_t stb = sb + s * STAGE;
#pragma unroll
        for (int it = 0; it < 2; it++) {
            int q = bq + it;
            uint32_t off = (uint32_t)(br * ROWB + q * 16);
            size_t idx = (size_t)br * K + c * 32 + q * 8;
            cp_async16(stb + 2 * AHALF + off, Bh + idx);
            cp_async16(stb + 3 * AHALF + off, Bl + idx);
        }
        CP_COMMIT();
    };

    auto ldgA = [&](int c, float4* pa) {
#pragma unroll
        for (int it = 0; it < 4; it++) {
            int q = aq + it;
            int row = rowBase + ar;
            float4 v = make_float4(0.f, 0.f, 0.f, 0.f);
            if (row < NN)
                v = *reinterpret_cast<const float4*>(&A[(size_t)row * K + c * 32 + q * 4]);
            pa[it] = v;
        }
    };

    auto stsA = [&](int s, const float4* pa) {
        char* st = smem + s * STAGE;
#pragma unroll
        for (int it = 0; it < 4; it++) {
            int q = aq + it;
            float4 v = pa[it];
            __nv_bfloat162 h01 = __floats2bfloat162_rn(v.x, v.y);
            __nv_bfloat162 h23 = __floats2bfloat162_rn(v.z, v.w);
            float2 hf0 = __bfloat1622float2(h01);
            float2 hf1 = __bfloat1622float2(h23);
            __nv_bfloat162 l01 = __floats2bfloat162_rn(v.x - hf0.x, v.y - hf0.y);
            __nv_bfloat162 l23 = __floats2bfloat162_rn(v.z - hf1.x, v.w - hf1.y);
            uint32_t off = (uint32_t)(ar * ROWB + q * 8);
            *reinterpret_cast<__nv_bfloat162*>(st + off)             = h01;
            *reinterpret_cast<__nv_bfloat162*>(st + off + 4)         = h23;
            *reinterpret_cast<__nv_bfloat162*>(st + AHALF + off)     = l01;
            *reinterpret_cast<__nv_bfloat162*>(st + AHALF + off + 4) = l23;
        }
    };

    {   // prologue: chunk 0 -> stage 0
        float4 pa[4];
        ldgA(0, pa);
        cpB(0, 0);
        stsA(0, pa);
        CP_WAIT0();
    }
    __syncthreads();

    for (int c = 0; c < NCH; c++) {
        const int s = c & 1;
        float4 pa[4];
        if (c + 1 < NCH) {
            ldgA(c + 1, pa);
            cpB(c + 1, s ^ 1);
        }

        const uint32_t aBaseH = sb + s * STAGE + (uint32_t)(warp_m * 32) * ROWB;
        const uint32_t bBaseH = sb + s * STAGE + 2 * AHALF + (uint32_t)(warp_n * 64) * ROWB;

#pragma unroll
        for (int sk = 0; sk < 2; sk++) {
            uint32_t ah[2][4], al[2][4];
#pragma unroll
            for (int t = 0; t < 2; t++) {
                uint32_t ad = aBaseH + (uint32_t)(t * 16 * ROWB + sk * 32) + a_off;
                LDSM_X4(ah[t][0], ah[t][1], ah[t][2], ah[t][3], ad);
                LDSM_X4(al[t][0], al[t][1], al[t][2], al[t][3], ad + AHALF);
            }
#pragma unroll
            for (int jp = 0; jp < 4; jp++) {       // B frags loaded per-pair (low regs)
                uint32_t bh[4], bl[4];
                uint32_t bd = bBaseH + (uint32_t)(jp * 16 * ROWB + sk * 32) + b_off;
                LDSM_X4(bh[0], bh[1], bh[2], bh[3], bd);
                LDSM_X4(bl[0], bl[1], bl[2], bl[3], bd + AHALF);
#pragma unroll
                for (int t = 0; t < 2; t++)
#pragma unroll
                    for (int jj = 0; jj < 2; jj++) {
                        int j = jp * 2 + jj, o = jj * 2;
                        MMA_BF16(acc[t][j], ah[t], bh[o], bh[o + 1]);
                        MMA_BF16(acc[t][j], ah[t], bl[o], bl[o + 1]);
                        MMA_BF16(acc[t][j], al[t], bh[o], bh[o + 1]);
                    }
            }
        }

        if (c + 1 < NCH) {
            stsA(s ^ 1, pa);
            CP_WAIT0();
        }
        __syncthreads();
    }

    // epilogue: fp16 stores
    const int r0 = rowBase + warp_m * 32 + (lane >> 2);
    const int cb = (lane & 3) * 2;
#pragma unroll
    for (int t = 0; t < 2; t++) {
#pragma unroll
        for (int j = 0; j < 8; j++) {
            int col = warp_n * 64 + j * 8 + cb;
            int ra = r0 + t * 16;
            int rb = ra + 8;
            if (ra < NN)
                *reinterpret_cast<__half2*>(&C[(size_t)ra * 128 + col]) =
                    __floats2half2_rn(acc[t][j][0], acc[t][j][1]);
            if (rb < NN)
                *reinterpret_cast<__half2*>(&C[(size_t)rb * 128 + col]) =
                    __floats2half2_rn(acc[t][j][2], acc[t][j][3]);
        }
    }
}

// ---------------- aggregation (fp16 gathers, fp32 accumulate) --------------
// MODE 1: O = relu(sum + biasA), fp32 [node][128]
// MODE 2: cols 0-63 -> OA + biasA, cols 64-127 -> OB + biasB (fp32 [node][64])
template <int MODE>
__global__ __launch_bounds__(256) void k_agg(
    const uint2* __restrict__ G,   // fp16 table: [node][32] x 8B
    const float* __restrict__ biasA, const float* __restrict__ biasB,
    float* __restrict__ OA, float* __restrict__ OB)
{
    int node = (blockIdx.x * blockDim.x + threadIdx.x) >> 5;
    int lane = threadIdx.x & 31;
    if (node >= NN) return;
    int n = g_cnt[node];
    n = (n < CAP) ? n : CAP;
    const int base = node << 7;
    float dd = g_dis[node];
    float w0 = dd * dd;
    uint2 r = G[(size_t)node * 32 + lane];
    float2 p0 = __half22float2(*reinterpret_cast<__half2*>(&r.x));
    float2 p1 = __half22float2(*reinterpret_cast<__half2*>(&r.y));
    float4 acc = make_float4(w0 * p0.x, w0 * p0.y, w0 * p1.x, w0 * p1.y);
#pragma unroll 4
    for (int j = 0; j < n; j++) {
        int   s = g_src[base + j];           // warp-broadcast
        float w = g_dis[s] * dd;             // warp-broadcast
        uint2 m = G[(size_t)s * 32 + lane];
        float2 q0 = __half22float2(*reinterpret_cast<__half2*>(&m.x));
        float2 q1 = __half22float2(*reinterpret_cast<__half2*>(&m.y));
        acc.x = fmaf(w, q0.x, acc.x);
        acc.y = fmaf(w, q0.y, acc.y);
        acc.z = fmaf(w, q1.x, acc.z);
        acc.w = fmaf(w, q1.y, acc.w);
    }
    if (MODE == 1) {
        float4 b = reinterpret_cast<const float4*>(biasA)[lane];
        acc.x = fmaxf(acc.x + b.x, 0.f);
        acc.y = fmaxf(acc.y + b.y, 0.f);
        acc.z = fmaxf(acc.z + b.z, 0.f);
        acc.w = fmaxf(acc.w + b.w, 0.f);
        reinterpret_cast<float4*>(OA)[(size_t)node * 32 + lane] = acc;
    } else {
        if (lane < 16) {
            float4 b = reinterpret_cast<const float4*>(biasA)[lane];
            acc.x += b.x; acc.y += b.y; acc.z += b.z; acc.w += b.w;
            reinterpret_cast<float4*>(OA)[(size_t)node * 16 + lane] = acc;
        } else {
            float4 b = reinterpret_cast<const float4*>(biasB)[lane - 16];
            acc.x += b.x; acc.y += b.y; acc.z += b.z; acc.w += b.w;
            reinterpret_cast<float4*>(OB)[(size_t)node * 16 + (lane - 16)] = acc;
        }
    }
}

// ---------------- launch ----------------------------------------------------
extern "C" void kernel_launch(void* const* d_in, const int* in_sizes, int n_in,
                              void* d_out, int out_size) {
    const float* x  = (const float*)d_in[0];
    const void*  ei = d_in[1];
    const float* W1 = (const float*)d_in[2];
    const float* b1 = (const float*)d_in[3];
    const float* W2 = (const float*)d_in[4];
    const float* b2 = (const float*)d_in[5];
    const float* Wm = (const float*)d_in[6];
    const float* bm = (const float*)d_in[7];
    const float* Ws = (const float*)d_in[8];
    const float* bs = (const float*)d_in[9];
    float* outM = (float*)d_out;
    float* outS = outM + (long)NN * ZD;

    float*  pA  = nullptr;
    __half* pH  = nullptr;
    __nv_bfloat16 *pBh = nullptr, *pBl = nullptr;
    cudaGetSymbolAddress((void**)&pA,  g_bufA);
    cudaGetSymbolAddress((void**)&pH,  g_H16);
    cudaGetSymbolAddress((void**)&pBh, g_Bh16);
    cudaGetSymbolAddress((void**)&pBl, g_Bl16);

    cudaFuncSetAttribute(k_tgemm<512>, cudaFuncAttributeMaxDynamicSharedMemorySize, GEMM_SMEM);
    cudaFuncSetAttribute(k_tgemm<128>, cudaFuncAttributeMaxDynamicSharedMemorySize, GEMM_SMEM);

    const int T = 256;
    const int gb = (NN + 127) / 128;           // 391 CTAs
    const int ab = (NN * 32 + T - 1) / T;      // agg blocks

    // preprocessing: bucket CSR + weights + dis (3 launches)
    k_init<<<(NN + T - 1) / T, T>>>((const int*)ei);
    k_fillcnt<<<(EE + T - 1) / T, T>>>(ei);
    k_prep2<<<384, 256>>>(W1, W2, Wm, Ws);

    // layer 1: H16 = fp16(x @ W1) ; h1 = relu(A H16 + b1)
    k_tgemm<512><<<gb, 256, GEMM_SMEM>>>(x, pBh, pBl, pH);
    k_agg<1><<<ab, T>>>((const uint2*)pH, b1, nullptr, pA, nullptr);
    // layer 2: H16 = fp16(h1 @ W2) ; h2 = relu(A H16 + b2)
    k_tgemm<128><<<gb, 256, GEMM_SMEM>>>(pA, pBh + 65536, pBl + 65536, pH);
    k_agg<1><<<ab, T>>>((const uint2*)pH, b2, nullptr, pA, nullptr);
    // heads: H16 = fp16(h2 @ [Wm|Ws]) ; [z_mean|z_log_std] = A H16 + [bm|bs]
    k_tgemm<128><<<gb, 256, GEMM_SMEM>>>(pA, pBh + 81920, pBl + 81920, pH);
    k_agg<2><<<ab, T>>>((const uint2*)pH, bm, bs, outM, outS);
}

// round 10
// speedup vs baseline: 1.2207x; 1.0200x over previous
#include <cuda_runtime.h>
#include <cuda_bf16.h>
#include <cuda_fp16.h>
#include <cstdint>

#define NN 50000
#define EE 800000
#define FD 128
#define ZD 64
#define CAP 128          // bucket capacity per node (Poisson(16); overflow ~1e-18)

static constexpr int GB = (NN + 127) / 128;          // 391 GEMM tiles
static constexpr int EB = (EE + 255) / 256;          // 3125 edge blocks

// ---------------- scratch (device globals; no allocation allowed) ----------
__device__ __align__(256) float  g_bufA[NN * FD];    // aliased: bf16 Ah | Al
__device__ __align__(256) __half g_H16[NN * FD];
__device__ __align__(256) __nv_bfloat16 g_Bh16[128 * 512 + 2 * 128 * 128];
__device__ __align__(256) __nv_bfloat16 g_Bl16[128 * 512 + 2 * 128 * 128];
__device__ __align__(256) int    g_src[NN * CAP];
__device__ int   g_cnt[NN];
__device__ float g_dis[NN];
__device__ int   g_is64;

// ---------------- PTX helpers ----------------------------------------------
__device__ __forceinline__ uint32_t smem_u32(const void* p) {
    uint32_t a;
    asm("{ .reg .u64 t; cvta.to.shared.u64 t, %1; cvt.u32.u64 %0, t; }"
        : "=r"(a) : "l"(p));
    return a;
}

__device__ __forceinline__ void cp_async16(uint32_t dst, const void* src) {
    asm volatile("cp.async.ca.shared.global [%0], [%1], 16;"
                 :: "r"(dst), "l"(src));
}
#define CP_COMMIT() asm volatile("cp.async.commit_group;")
#define CP_WAIT0()  asm volatile("cp.async.wait_group 0;" ::: "memory")

#define LDSM_X4(r0, r1, r2, r3, addr) \
    asm volatile("ldmatrix.sync.aligned.m8n8.x4.shared.b16 {%0,%1,%2,%3}, [%4];" \
        : "=r"(r0), "=r"(r1), "=r"(r2), "=r"(r3) : "r"(addr))

#define MMA_BF16(d, a, b0, b1) \
    asm volatile("mma.sync.aligned.m16n8k16.row.col.f32.bf16.bf16.f32 " \
        "{%0,%1,%2,%3}, {%4,%5,%6,%7}, {%8,%9}, {%0,%1,%2,%3};" \
        : "+f"((d)[0]), "+f"((d)[1]), "+f"((d)[2]), "+f"((d)[3]) \
        : "r"((a)[0]), "r"((a)[1]), "r"((a)[2]), "r"((a)[3]), "r"(b0), "r"(b1))

// ---------------- preprocessing --------------------------------------------
__device__ __forceinline__ int edge_at(const void* eiv, long idx) {
    if (g_is64) return (int)((const long long*)eiv)[idx];
    return ((const int*)eiv)[idx];
}

// zero counts + detect dtype + split all weights to bf16 hi/lo [N=128][K]
__global__ void k_init(const int* __restrict__ ei32,
                       const float* __restrict__ W1, const float* __restrict__ W2,
                       const float* __restrict__ Wm, const float* __restrict__ Ws) {
    int i = blockIdx.x * blockDim.x + threadIdx.x;    // 384*256 = 98304
    if (i < NN) g_cnt[i] = 0;
    if (blockIdx.x == 0 && threadIdx.x < 32) {
        int v = ei32[2 * threadIdx.x + 1];
        unsigned m = __ballot_sync(0xffffffffu, v != 0);
        if (threadIdx.x == 0) g_is64 = (m == 0) ? 1 : 0;
    }
    float v;
    if (i < 65536) {
        int n = i >> 9, k = i & 511;
        v = W1[k * 128 + n];
    } else if (i < 81920) {
        int idx = i - 65536;
        int n = idx >> 7, k = idx & 127;
        v = W2[k * 128 + n];
    } else {
        int idx = i - 81920;
        int n = idx >> 7, k = idx & 127;
        v = (n < 64) ? Wm[k * 64 + n] : Ws[k * 64 + (n - 64)];
    }
    __nv_bfloat16 h = __float2bfloat16_rn(v);
    __nv_bfloat16 l = __float2bfloat16_rn(v - __bfloat162float(h));
    g_Bh16[i] = h;
    g_Bl16[i] = l;
}

// dis = rsqrt(deg+1), after counts complete
__global__ void k_dis() {
    int i = blockIdx.x * blockDim.x + threadIdx.x;
    if (i < NN) g_dis[i] = rsqrtf((float)(g_cnt[i] + 1));
}

// ---------------- bf16 split-3 tensor-core GEMM, fp16 output ---------------
// C_fp16[M x 128] = A[M x K] @ B[K x 128]; 128x128 CTA tile, 8 warps of 32x64.
// FUSE: blocks >= GB run the edge scatter (bucket CSR fill) instead.
// APRE: A is pre-split bf16 hi/lo in global (from k_agg) -> cp.async path.
static constexpr int ROWB   = 80;                 // padded bf16 row (conflict-free ldmatrix)
static constexpr int AHALF  = 128 * ROWB;         // 10240
static constexpr int STAGE  = 4 * AHALF;          // Ah | Al | Bh | Bl
static constexpr int GEMM_SMEM = 2 * STAGE;       // 81920

template <int K, int FUSE, int APRE>
__global__ __launch_bounds__(256, 2) void k_tgemm(
    const float* __restrict__ A,
    const __nv_bfloat16* __restrict__ Ah, const __nv_bfloat16* __restrict__ Al,
    const __nv_bfloat16* __restrict__ Bh, const __nv_bfloat16* __restrict__ Bl,
    __half* __restrict__ C, const void* __restrict__ eiv)
{
    if (FUSE && blockIdx.x >= GB) {                 // edge-scatter role
        int e = (blockIdx.x - GB) * 256 + threadIdx.x;
        if (e < EE) {
            int s = edge_at(eiv, e);
            int d = edge_at(eiv, (long)EE + e);
            int pos = atomicAdd(&g_cnt[d], 1);
            if (pos < CAP) g_src[(d << 7) + pos] = s;
        }
        return;
    }

    extern __shared__ __align__(256) char smem[];
    constexpr int NCH = K / 32;
    const int tid  = threadIdx.x;
    const int wid  = tid >> 5;
    const int lane = tid & 31;
    const int warp_m = wid & 3;
    const int warp_n = wid >> 2;
    const uint32_t sb = smem_u32(smem);
    const int rowBase = blockIdx.x * 128;

    const uint32_t a_off = (uint32_t)(((lane & 7) + ((lane >> 3) & 1) * 8) * ROWB
                                      + ((lane >> 4) & 1) * 16);
    const uint32_t b_off = (uint32_t)((((lane >> 4) & 1) * 8 + (lane & 7)) * ROWB
                                      + ((lane >> 3) & 1) * 16);

    float acc[2][8][4];
#pragma unroll
    for (int t = 0; t < 2; t++)
#pragma unroll
        for (int j = 0; j < 8; j++)
#pragma unroll
            for (int v = 0; v < 4; v++) acc[t][j][v] = 0.f;

    const int ar = tid >> 1;          // A: 128 rows, 2 thr/row
    const int aq = (tid & 1) * 4;     // A fp32 path: quad base (4 iters)
    const int br = tid >> 1;          // A/B cp path: 128 rows
    const int bq = (tid & 1) << 1;    // 16B chunk base (2 iters)

    auto cpB = [&](int c, int s) {
        uint32_t stb = sb + s * STAGE;
#pragma unroll
        for (int it = 0; it < 2; it++) {
            int q = bq + it;
            uint32_t off = (uint32_t)(br * ROWB + q * 16);
            size_t idx = (size_t)br * K + c * 32 + q * 8;
            cp_async16(stb + 2 * AHALF + off, Bh + idx);
            cp_async16(stb + 3 * AHALF + off, Bl + idx);
        }
        CP_COMMIT();
    };

    auto cpA = [&](int c, int s) {    // APRE path
        uint32_t stb = sb + s * STAGE;
        int row = rowBase + br;
        if (row < NN) {
#pragma unroll
            for (int it = 0; it < 2; it++) {
                int q = bq + it;
                uint32_t off = (uint32_t)(br * ROWB + q * 16);
                size_t idx = (size_t)row * K + c * 32 + q * 8;
                cp_async16(stb + off, Ah + idx);
                cp_async16(stb + AHALF + off, Al + idx);
            }
        }
        CP_COMMIT();
    };

    auto ldgA = [&](int c, float4* pa) {
#pragma unroll
        for (int it = 0; it < 4; it++) {
            int q = aq + it;
            int row = rowBase + ar;
            float4 v = make_float4(0.f, 0.f, 0.f, 0.f);
            if (row < NN)
                v = *reinterpret_cast<const float4*>(&A[(size_t)row * K + c * 32 + q * 4]);
            pa[it] = v;
        }
    };

    auto stsA = [&](int s, const float4* pa) {
        char* st = smem + s * STAGE;
#pragma unroll
        for (int it = 0; it < 4; it++) {
            int q = aq + it;
            float4 v = pa[it];
            __nv_bfloat162 h01 = __floats2bfloat162_rn(v.x, v.y);
            __nv_bfloat162 h23 = __floats2bfloat162_rn(v.z, v.w);
            float2 hf0 = __bfloat1622float2(h01);
            float2 hf1 = __bfloat1622float2(h23);
            __nv_bfloat162 l01 = __floats2bfloat162_rn(v.x - hf0.x, v.y - hf0.y);
            __nv_bfloat162 l23 = __floats2bfloat162_rn(v.z - hf1.x, v.w - hf1.y);
            uint32_t off = (uint32_t)(ar * ROWB + q * 8);
            *reinterpret_cast<__nv_bfloat162*>(st + off)             = h01;
            *reinterpret_cast<__nv_bfloat162*>(st + off + 4)         = h23;
            *reinterpret_cast<__nv_bfloat162*>(st + AHALF + off)     = l01;
            *reinterpret_cast<__nv_bfloat162*>(st + AHALF + off + 4) = l23;
        }
    };

    {   // prologue: chunk 0 -> stage 0
        if (APRE) {
            cpA(0, 0);
            cpB(0, 0);
        } else {
            float4 pa[4];
            ldgA(0, pa);
            cpB(0, 0);
            stsA(0, pa);
        }
        CP_WAIT0();
    }
    __syncthreads();

    for (int c = 0; c < NCH; c++) {
        const int s = c & 1;
        float4 pa[4];
        if (c + 1 < NCH) {
            if (APRE) {
                cpA(c + 1, s ^ 1);
                cpB(c + 1, s ^ 1);
            } else {
                ldgA(c + 1, pa);
                cpB(c + 1, s ^ 1);
            }
        }

        const uint32_t aBaseH = sb + s * STAGE + (uint32_t)(warp_m * 32) * ROWB;
        const uint32_t bBaseH = sb + s * STAGE + 2 * AHALF + (uint32_t)(warp_n * 64) * ROWB;

#pragma unroll
        for (int sk = 0; sk < 2; sk++) {
            uint32_t ah[2][4], al[2][4];
#pragma unroll
            for (int t = 0; t < 2; t++) {
                uint32_t ad = aBaseH + (uint32_t)(t * 16 * ROWB + sk * 32) + a_off;
                LDSM_X4(ah[t][0], ah[t][1], ah[t][2], ah[t][3], ad);
                LDSM_X4(al[t][0], al[t][1], al[t][2], al[t][3], ad + AHALF);
            }
#pragma unroll
            for (int jp = 0; jp < 4; jp++) {
                uint32_t bh[4], bl[4];
                uint32_t bd = bBaseH + (uint32_t)(jp * 16 * ROWB + sk * 32) + b_off;
                LDSM_X4(bh[0], bh[1], bh[2], bh[3], bd);
                LDSM_X4(bl[0], bl[1], bl[2], bl[3], bd + AHALF);
#pragma unroll
                for (int t = 0; t < 2; t++)
#pragma unroll
                    for (int jj = 0; jj < 2; jj++) {
                        int j = jp * 2 + jj, o = jj * 2;
                        MMA_BF16(acc[t][j], ah[t], bh[o], bh[o + 1]);
                        MMA_BF16(acc[t][j], ah[t], bl[o], bl[o + 1]);
                        MMA_BF16(acc[t][j], al[t], bh[o], bh[o + 1]);
                    }
            }
        }

        if (c + 1 < NCH) {
            if (!APRE) stsA(s ^ 1, pa);
            CP_WAIT0();
        }
        __syncthreads();
    }

    // epilogue: fp16 stores
    const int r0 = rowBase + warp_m * 32 + (lane >> 2);
    const int cb = (lane & 3) * 2;
#pragma unroll
    for (int t = 0; t < 2; t++) {
#pragma unroll
        for (int j = 0; j < 8; j++) {
            int col = warp_n * 64 + j * 8 + cb;
            int ra = r0 + t * 16;
            int rb = ra + 8;
            if (ra < NN)
                *reinterpret_cast<__half2*>(&C[(size_t)ra * 128 + col]) =
                    __floats2half2_rn(acc[t][j][0], acc[t][j][1]);
            if (rb < NN)
                *reinterpret_cast<__half2*>(&C[(size_t)rb * 128 + col]) =
                    __floats2half2_rn(acc[t][j][2], acc[t][j][3]);
        }
    }
}

// ---------------- aggregation (fp16 gathers, fp32 accumulate) --------------
// MODE 1: h = relu(sum + biasA) -> bf16 hi/lo split arrays (GEMM A input)
// MODE 2: cols 0-63 -> OA + biasA, cols 64-127 -> OB + biasB (fp32 [node][64])
template <int MODE>
__global__ __launch_bounds__(256) void k_agg(
    const uint2* __restrict__ G,   // fp16 table: [node][32] x 8B
    const float* __restrict__ biasA, const float* __restrict__ biasB,
    float* __restrict__ OA, float* __restrict__ OB,
    __nv_bfloat16* __restrict__ Hh, __nv_bfloat16* __restrict__ Hl)
{
    int node = (blockIdx.x * blockDim.x + threadIdx.x) >> 5;
    int lane = threadIdx.x & 31;
    if (node >= NN) return;
    int n = g_cnt[node];
    n = (n < CAP) ? n : CAP;
    const int base = node << 7;
    float dd = g_dis[node];
    float w0 = dd * dd;
    uint2 r = G[(size_t)node * 32 + lane];
    float2 p0 = __half22float2(*reinterpret_cast<__half2*>(&r.x));
    float2 p1 = __half22float2(*reinterpret_cast<__half2*>(&r.y));
    float4 acc = make_float4(w0 * p0.x, w0 * p0.y, w0 * p1.x, w0 * p1.y);
#pragma unroll 8
    for (int j = 0; j < n; j++) {
        int   s = g_src[base + j];           // warp-broadcast
        float w = g_dis[s] * dd;             // warp-broadcast
        uint2 m = G[(size_t)s * 32 + lane];
        float2 q0 = __half22float2(*reinterpret_cast<__half2*>(&m.x));
        float2 q1 = __half22float2(*reinterpret_cast<__half2*>(&m.y));
        acc.x = fmaf(w, q0.x, acc.x);
        acc.y = fmaf(w, q0.y, acc.y);
        acc.z = fmaf(w, q1.x, acc.z);
        acc.w = fmaf(w, q1.y, acc.w);
    }
    if (MODE == 1) {
        float4 b = reinterpret_cast<const float4*>(biasA)[lane];
        acc.x = fmaxf(acc.x + b.x, 0.f);
        acc.y = fmaxf(acc.y + b.y, 0.f);
        acc.z = fmaxf(acc.z + b.z, 0.f);
        acc.w = fmaxf(acc.w + b.w, 0.f);
        // split to bf16 hi/lo for next GEMM's cp.async A path
        __nv_bfloat162 h01 = __floats2bfloat162_rn(acc.x, acc.y);
        __nv_bfloat162 h23 = __floats2bfloat162_rn(acc.z, acc.w);
        float2 hf0 = __bfloat1622float2(h01);
        float2 hf1 = __bfloat1622float2(h23);
        __nv_bfloat162 l01 = __floats2bfloat162_rn(acc.x - hf0.x, acc.y - hf0.y);
        __nv_bfloat162 l23 = __floats2bfloat162_rn(acc.z - hf1.x, acc.w - hf1.y);
        size_t o = (size_t)node * 128 + lane * 4;
        uint2 hv, lv;
        hv.x = *reinterpret_cast<uint32_t*>(&h01);
        hv.y = *reinterpret_cast<uint32_t*>(&h23);
        lv.x = *reinterpret_cast<uint32_t*>(&l01);
        lv.y = *reinterpret_cast<uint32_t*>(&l23);
        *reinterpret_cast<uint2*>(Hh + o) = hv;
        *reinterpret_cast<uint2*>(Hl + o) = lv;
    } else {
        if (lane < 16) {
            float4 b = reinterpret_cast<const float4*>(biasA)[lane];
            acc.x += b.x; acc.y += b.y; acc.z += b.z; acc.w += b.w;
            reinterpret_cast<float4*>(OA)[(size_t)node * 16 + lane] = acc;
        } else {
            float4 b = reinterpret_cast<const float4*>(biasB)[lane - 16];
            acc.x += b.x; acc.y += b.y; acc.z += b.z; acc.w += b.w;
            reinterpret_cast<float4*>(OB)[(size_t)node * 16 + (lane - 16)] = acc;
        }
    }
}

// ---------------- launch ----------------------------------------------------
extern "C" void kernel_launch(void* const* d_in, const int* in_sizes, int n_in,
                              void* d_out, int out_size) {
    const float* x  = (const float*)d_in[0];
    const void*  ei = d_in[1];
    const float* W1 = (const float*)d_in[2];
    const float* b1 = (const float*)d_in[3];
    const float* W2 = (const float*)d_in[4];
    const float* b2 = (const float*)d_in[5];
    const float* Wm = (const float*)d_in[6];
    const float* bm = (const float*)d_in[7];
    const float* Ws = (const float*)d_in[8];
    const float* bs = (const float*)d_in[9];
    float* outM = (float*)d_out;
    float* outS = outM + (long)NN * ZD;

    float*  pA  = nullptr;
    __half* pH  = nullptr;
    __nv_bfloat16 *pBh = nullptr, *pBl = nullptr;
    cudaGetSymbolAddress((void**)&pA,  g_bufA);
    cudaGetSymbolAddress((void**)&pH,  g_H16);
    cudaGetSymbolAddress((void**)&pBh, g_Bh16);
    cudaGetSymbolAddress((void**)&pBl, g_Bl16);
    __nv_bfloat16* pAh = (__nv_bfloat16*)pA;             // alias g_bufA
    __nv_bfloat16* pAl = pAh + (size_t)NN * FD;

    cudaFuncSetAttribute(k_tgemm<512, 1, 0>, cudaFuncAttributeMaxDynamicSharedMemorySize, GEMM_SMEM);
    cudaFuncSetAttribute(k_tgemm<128, 0, 1>, cudaFuncAttributeMaxDynamicSharedMemorySize, GEMM_SMEM);

    const int T = 256;
    const int ab = (NN * 32 + T - 1) / T;      // agg blocks

    // init: zero counts + dtype detect + all weight splits (1 launch)
    k_init<<<384, T>>>((const int*)ei, W1, W2, Wm, Ws);

    // GEMM1 fused with edge scatter (tail absorption)
    k_tgemm<512, 1, 0><<<GB + EB, T, GEMM_SMEM>>>(x, nullptr, nullptr, pBh, pBl, pH, ei);
    k_dis<<<(NN + T - 1) / T, T>>>();
    k_agg<1><<<ab, T>>>((const uint2*)pH, b1, nullptr, nullptr, nullptr, pAh, pAl);
    // layer 2
    k_tgemm<128, 0, 1><<<GB, T, GEMM_SMEM>>>(nullptr, pAh, pAl, pBh + 65536, pBl + 65536, pH, nullptr);
    k_agg<1><<<ab, T>>>((const uint2*)pH, b2, nullptr, nullptr, nullptr, pAh, pAl);
    // heads
    k_tgemm<128, 0, 1><<<GB, T, GEMM_SMEM>>>(nullptr, pAh, pAl, pBh + 81920, pBl + 81920, pH, nullptr);
    k_agg<2><<<ab, T>>>((const uint2*)pH, bm, bs, outM, outS, nullptr, nullptr);
}

// round 11
// speedup vs baseline: 1.3416x; 1.0990x over previous
#include <cuda_runtime.h>
#include <cuda_bf16.h>
#include <cuda_fp16.h>
#include <cstdint>

#define NN 50000
#define EE 800000
#define FD 128
#define ZD 64
#define CAP 128          // bucket capacity per node (Poisson(16); overflow ~1e-18)

static constexpr int GB = (NN + 127) / 128;          // 391 GEMM tiles
static constexpr int EB = (EE + 255) / 256;          // 3125 edge blocks

// ---------------- scratch (device globals; no allocation allowed) ----------
__device__ __align__(256) float  g_bufA[NN * FD];    // aliased: fp16 Ah | Al
__device__ __align__(256) __half g_H16[NN * FD];
__device__ __align__(256) __half g_Bf16[128 * 512 + 2 * 128 * 128];
__device__ __align__(256) int    g_src[NN * CAP];
__device__ __align__(256) float  g_wt[NN * CAP];
__device__ int   g_cnt[NN];
__device__ float g_dis[NN];
__device__ int   g_is64;

// ---------------- PTX helpers ----------------------------------------------
__device__ __forceinline__ uint32_t smem_u32(const void* p) {
    uint32_t a;
    asm("{ .reg .u64 t; cvta.to.shared.u64 t, %1; cvt.u32.u64 %0, t; }"
        : "=r"(a) : "l"(p));
    return a;
}

__device__ __forceinline__ void cp_async16(uint32_t dst, const void* src) {
    asm volatile("cp.async.ca.shared.global [%0], [%1], 16;"
                 :: "r"(dst), "l"(src));
}
#define CP_COMMIT() asm volatile("cp.async.commit_group;")
#define CP_WAIT0()  asm volatile("cp.async.wait_group 0;" ::: "memory")

#define LDSM_X4(r0, r1, r2, r3, addr) \
    asm volatile("ldmatrix.sync.aligned.m8n8.x4.shared.b16 {%0,%1,%2,%3}, [%4];" \
        : "=r"(r0), "=r"(r1), "=r"(r2), "=r"(r3) : "r"(addr))

#define MMA_F16(d, a, b0, b1) \
    asm volatile("mma.sync.aligned.m16n8k16.row.col.f32.f16.f16.f32 " \
        "{%0,%1,%2,%3}, {%4,%5,%6,%7}, {%8,%9}, {%0,%1,%2,%3};" \
        : "+f"((d)[0]), "+f"((d)[1]), "+f"((d)[2]), "+f"((d)[3]) \
        : "r"((a)[0]), "r"((a)[1]), "r"((a)[2]), "r"((a)[3]), "r"(b0), "r"(b1))

// ---------------- preprocessing --------------------------------------------
__device__ __forceinline__ int edge_at(const void* eiv, long idx) {
    if (g_is64) return (int)((const long long*)eiv)[idx];
    return ((const int*)eiv)[idx];
}

// zero counts + detect dtype + weights -> fp16 [N=128][K]
__global__ void k_init(const int* __restrict__ ei32,
                       const float* __restrict__ W1, const float* __restrict__ W2,
                       const float* __restrict__ Wm, const float* __restrict__ Ws) {
    int i = blockIdx.x * blockDim.x + threadIdx.x;    // 384*256 = 98304
    if (i < NN) g_cnt[i] = 0;
    if (blockIdx.x == 0 && threadIdx.x < 32) {
        int v = ei32[2 * threadIdx.x + 1];
        unsigned m = __ballot_sync(0xffffffffu, v != 0);
        if (threadIdx.x == 0) g_is64 = (m == 0) ? 1 : 0;
    }
    float v;
    if (i < 65536) {
        int n = i >> 9, k = i & 511;
        v = W1[k * 128 + n];
    } else if (i < 81920) {
        int idx = i - 65536;
        int n = idx >> 7, k = idx & 127;
        v = W2[k * 128 + n];
    } else {
        int idx = i - 81920;
        int n = idx >> 7, k = idx & 127;
        v = (n < 64) ? Wm[k * 64 + n] : Ws[k * 64 + (n - 64)];
    }
    g_Bf16[i] = __float2half_rn(v);
}

// dis = rsqrt(deg+1), after counts complete
__global__ void k_dis() {
    int i = blockIdx.x * blockDim.x + threadIdx.x;
    if (i < NN) g_dis[i] = rsqrtf((float)(g_cnt[i] + 1));
}

// ---------------- fp16 split-2 tensor-core GEMM, fp16 output ---------------
// C = (Ah+Al) @ B ; A split-2 fp16 (error ~2^-21), B single fp16.
// 128x128 CTA tile, 8 warps of 32x64. FUSE: blocks >= GB run edge scatter.
// APRE: A pre-split fp16 hi/lo in global (from k_agg) -> cp.async path.
static constexpr int ROWB   = 80;                 // padded 32-elem fp16 row
static constexpr int AHALF  = 128 * ROWB;         // 10240
static constexpr int STAGE  = 3 * AHALF;          // Ah | Al | Bf = 30720
static constexpr int GEMM_SMEM = 2 * STAGE;       // 61440

template <int K, int FUSE, int APRE>
__global__ __launch_bounds__(256, 2) void k_tgemm(
    const float* __restrict__ A,
    const __half* __restrict__ Ah, const __half* __restrict__ Al,
    const __half* __restrict__ Bf,
    __half* __restrict__ C, const void* __restrict__ eiv)
{
    if (FUSE && blockIdx.x >= GB) {                 // edge-scatter role
        int e = (blockIdx.x - GB) * 256 + threadIdx.x;
        if (e < EE) {
            int s = edge_at(eiv, e);
            int d = edge_at(eiv, (long)EE + e);
            int pos = atomicAdd(&g_cnt[d], 1);
            if (pos < CAP) g_src[(d << 7) + pos] = s;
        }
        return;
    }

    extern __shared__ __align__(256) char smem[];
    constexpr int NCH = K / 32;
    const int tid  = threadIdx.x;
    const int wid  = tid >> 5;
    const int lane = tid & 31;
    const int warp_m = wid & 3;
    const int warp_n = wid >> 2;
    const uint32_t sb = smem_u32(smem);
    const int rowBase = blockIdx.x * 128;

    const uint32_t a_off = (uint32_t)(((lane & 7) + ((lane >> 3) & 1) * 8) * ROWB
                                      + ((lane >> 4) & 1) * 16);
    const uint32_t b_off = (uint32_t)((((lane >> 4) & 1) * 8 + (lane & 7)) * ROWB
                                      + ((lane >> 3) & 1) * 16);

    float acc[2][8][4];
#pragma unroll
    for (int t = 0; t < 2; t++)
#pragma unroll
        for (int j = 0; j < 8; j++)
#pragma unroll
            for (int v = 0; v < 4; v++) acc[t][j][v] = 0.f;

    const int ar = tid >> 1;          // 128 rows, 2 thr/row
    const int aq = (tid & 1) * 4;     // fp32 A path: quad base (4 iters)
    const int br = tid >> 1;
    const int bq = (tid & 1) << 1;    // 16B chunk base (2 iters)

    auto cpB = [&](int c, int s) {
        uint32_t stb = sb + s * STAGE;
#pragma unroll
        for (int it = 0; it < 2; it++) {
            int q = bq + it;
            uint32_t off = (uint32_t)(br * ROWB + q * 16);
            size_t idx = (size_t)br * K + c * 32 + q * 8;
            cp_async16(stb + 2 * AHALF + off, Bf + idx);
        }
        CP_COMMIT();
    };

    auto cpA = [&](int c, int s) {    // APRE path
        uint32_t stb = sb + s * STAGE;
        int row = rowBase + br;
        if (row < NN) {
#pragma unroll
            for (int it = 0; it < 2; it++) {
                int q = bq + it;
                uint32_t off = (uint32_t)(br * ROWB + q * 16);
                size_t idx = (size_t)row * K + c * 32 + q * 8;
                cp_async16(stb + off, Ah + idx);
                cp_async16(stb + AHALF + off, Al + idx);
            }
        }
        CP_COMMIT();
    };

    auto ldgA = [&](int c, float4* pa) {
#pragma unroll
        for (int it = 0; it < 4; it++) {
            int q = aq + it;
            int row = rowBase + ar;
            float4 v = make_float4(0.f, 0.f, 0.f, 0.f);
            if (row < NN)
                v = *reinterpret_cast<const float4*>(&A[(size_t)row * K + c * 32 + q * 4]);
            pa[it] = v;
        }
    };

    auto stsA = [&](int s, const float4* pa) {   // fp32 -> fp16 split-2
        char* st = smem + s * STAGE;
#pragma unroll
        for (int it = 0; it < 4; it++) {
            int q = aq + it;
            float4 v = pa[it];
            __half2 h01 = __floats2half2_rn(v.x, v.y);
            __half2 h23 = __floats2half2_rn(v.z, v.w);
            float2 hf0 = __half22float2(h01);
            float2 hf1 = __half22float2(h23);
            __half2 l01 = __floats2half2_rn(v.x - hf0.x, v.y - hf0.y);
            __half2 l23 = __floats2half2_rn(v.z - hf1.x, v.w - hf1.y);
            uint32_t off = (uint32_t)(ar * ROWB + q * 8);
            *reinterpret_cast<__half2*>(st + off)             = h01;
            *reinterpret_cast<__half2*>(st + off + 4)         = h23;
            *reinterpret_cast<__half2*>(st + AHALF + off)     = l01;
            *reinterpret_cast<__half2*>(st + AHALF + off + 4) = l23;
        }
    };

    {   // prologue: chunk 0 -> stage 0
        if (APRE) {
            cpA(0, 0);
            cpB(0, 0);
        } else {
            float4 pa[4];
            ldgA(0, pa);
            cpB(0, 0);
            stsA(0, pa);
        }
        CP_WAIT0();
    }
    __syncthreads();

    for (int c = 0; c < NCH; c++) {
        const int s = c & 1;
        float4 pa[4];
        if (c + 1 < NCH) {
            if (APRE) {
                cpA(c + 1, s ^ 1);
                cpB(c + 1, s ^ 1);
            } else {
                ldgA(c + 1, pa);
                cpB(c + 1, s ^ 1);
            }
        }

        const uint32_t aBaseH = sb + s * STAGE + (uint32_t)(warp_m * 32) * ROWB;
        const uint32_t bBaseH = sb + s * STAGE + 2 * AHALF + (uint32_t)(warp_n * 64) * ROWB;

#pragma unroll
        for (int sk = 0; sk < 2; sk++) {
            uint32_t ah[2][4], al[2][4];
#pragma unroll
            for (int t = 0; t < 2; t++) {
                uint32_t ad = aBaseH + (uint32_t)(t * 16 * ROWB + sk * 32) + a_off;
                LDSM_X4(ah[t][0], ah[t][1], ah[t][2], ah[t][3], ad);
                LDSM_X4(al[t][0], al[t][1], al[t][2], al[t][3], ad + AHALF);
            }
#pragma unroll
            for (int jp = 0; jp < 4; jp++) {
                uint32_t bf[4];
                uint32_t bd = bBaseH + (uint32_t)(jp * 16 * ROWB + sk * 32) + b_off;
                LDSM_X4(bf[0], bf[1], bf[2], bf[3], bd);
#pragma unroll
                for (int t = 0; t < 2; t++)
#pragma unroll
                    for (int jj = 0; jj < 2; jj++) {
                        int j = jp * 2 + jj, o = jj * 2;
                        MMA_F16(acc[t][j], ah[t], bf[o], bf[o + 1]);
                        MMA_F16(acc[t][j], al[t], bf[o], bf[o + 1]);
                    }
            }
        }

        if (c + 1 < NCH) {
            if (!APRE) stsA(s ^ 1, pa);
            CP_WAIT0();
        }
        __syncthreads();
    }

    // epilogue: fp16 stores
    const int r0 = rowBase + warp_m * 32 + (lane >> 2);
    const int cb = (lane & 3) * 2;
#pragma unroll
    for (int t = 0; t < 2; t++) {
#pragma unroll
        for (int j = 0; j < 8; j++) {
            int col = warp_n * 64 + j * 8 + cb;
            int ra = r0 + t * 16;
            int rb = ra + 8;
            if (ra < NN)
                *reinterpret_cast<__half2*>(&C[(size_t)ra * 128 + col]) =
                    __floats2half2_rn(acc[t][j][0], acc[t][j][1]);
            if (rb < NN)
                *reinterpret_cast<__half2*>(&C[(size_t)rb * 128 + col]) =
                    __floats2half2_rn(acc[t][j][2], acc[t][j][3]);
        }
    }
}

// ---------------- aggregation (fp16 gathers, fp32 accumulate) --------------
// MODE 1: h = relu(sum + biasA) -> fp16 hi/lo split arrays (next GEMM A input)
// MODE 2: cols 0-63 -> OA + biasA, cols 64-127 -> OB + biasB (fp32 [node][64])
// WST 1: compute w = dis[s]*dis[d], store to g_wt; WST 0: load w from g_wt.
template <int MODE, int WST>
__global__ __launch_bounds__(256) void k_agg(
    const uint2* __restrict__ G,   // fp16 table: [node][32] x 8B
    const float* __restrict__ biasA, const float* __restrict__ biasB,
    float* __restrict__ OA, float* __restrict__ OB,
    __half* __restrict__ Hh, __half* __restrict__ Hl)
{
    int node = (blockIdx.x * blockDim.x + threadIdx.x) >> 5;
    int lane = threadIdx.x & 31;
    if (node >= NN) return;
    int n = g_cnt[node];
    n = (n < CAP) ? n : CAP;
    const int base = node << 7;
    float dd = g_dis[node];
    float w0 = dd * dd;
    uint2 r = G[(size_t)node * 32 + lane];
    float2 p0 = __half22float2(*reinterpret_cast<__half2*>(&r.x));
    float2 p1 = __half22float2(*reinterpret_cast<__half2*>(&r.y));
    float4 acc = make_float4(w0 * p0.x, w0 * p0.y, w0 * p1.x, w0 * p1.y);
#pragma unroll 8
    for (int j = 0; j < n; j++) {
        float w;
        if (WST) {
            int s = g_src[base + j];
            w = g_dis[s] * dd;
            if (lane == 0) g_wt[base + j] = w;
            uint2 m = G[(size_t)s * 32 + lane];
            float2 q0 = __half22float2(*reinterpret_cast<__half2*>(&m.x));
            float2 q1 = __half22float2(*reinterpret_cast<__half2*>(&m.y));
            acc.x = fmaf(w, q0.x, acc.x);
            acc.y = fmaf(w, q0.y, acc.y);
            acc.z = fmaf(w, q1.x, acc.z);
            acc.w = fmaf(w, q1.y, acc.w);
        } else {
            int s = g_src[base + j];
            w = g_wt[base + j];
            uint2 m = G[(size_t)s * 32 + lane];
            float2 q0 = __half22float2(*reinterpret_cast<__half2*>(&m.x));
            float2 q1 = __half22float2(*reinterpret_cast<__half2*>(&m.y));
            acc.x = fmaf(w, q0.x, acc.x);
            acc.y = fmaf(w, q0.y, acc.y);
            acc.z = fmaf(w, q1.x, acc.z);
            acc.w = fmaf(w, q1.y, acc.w);
        }
    }
    if (MODE == 1) {
        float4 b = reinterpret_cast<const float4*>(biasA)[lane];
        acc.x = fmaxf(acc.x + b.x, 0.f);
        acc.y = fmaxf(acc.y + b.y, 0.f);
        acc.z = fmaxf(acc.z + b.z, 0.f);
        acc.w = fmaxf(acc.w + b.w, 0.f);
        // split to fp16 hi/lo for next GEMM's cp.async A path
        __half2 h01 = __floats2half2_rn(acc.x, acc.y);
        __half2 h23 = __floats2half2_rn(acc.z, acc.w);
        float2 hf0 = __half22float2(h01);
        float2 hf1 = __half22float2(h23);
        __half2 l01 = __floats2half2_rn(acc.x - hf0.x, acc.y - hf0.y);
        __half2 l23 = __floats2half2_rn(acc.z - hf1.x, acc.w - hf1.y);
        size_t o = (size_t)node * 128 + lane * 4;
        uint2 hv, lv;
        hv.x = *reinterpret_cast<uint32_t*>(&h01);
        hv.y = *reinterpret_cast<uint32_t*>(&h23);
        lv.x = *reinterpret_cast<uint32_t*>(&l01);
        lv.y = *reinterpret_cast<uint32_t*>(&l23);
        *reinterpret_cast<uint2*>(Hh + o) = hv;
        *reinterpret_cast<uint2*>(Hl + o) = lv;
    } else {
        if (lane < 16) {
            float4 b = reinterpret_cast<const float4*>(biasA)[lane];
            acc.x += b.x; acc.y += b.y; acc.z += b.z; acc.w += b.w;
            reinterpret_cast<float4*>(OA)[(size_t)node * 16 + lane] = acc;
        } else {
            float4 b = reinterpret_cast<const float4*>(biasB)[lane - 16];
            acc.x += b.x; acc.y += b.y; acc.z += b.z; acc.w += b.w;
            reinterpret_cast<float4*>(OB)[(size_t)node * 16 + (lane - 16)] = acc;
        }
    }
}

// ---------------- launch ----------------------------------------------------
extern "C" void kernel_launch(void* const* d_in, const int* in_sizes, int n_in,
                              void* d_out, int out_size) {
    const float* x  = (const float*)d_in[0];
    const void*  ei = d_in[1];
    const float* W1 = (const float*)d_in[2];
    const float* b1 = (const float*)d_in[3];
    const float* W2 = (const float*)d_in[4];
    const float* b2 = (const float*)d_in[5];
    const float* Wm = (const float*)d_in[6];
    const float* bm = (const float*)d_in[7];
    const float* Ws = (const float*)d_in[8];
    const float* bs = (const float*)d_in[9];
    float* outM = (float*)d_out;
    float* outS = outM + (long)NN * ZD;

    float*  pA  = nullptr;
    __half* pH  = nullptr;
    __half* pBf = nullptr;
    cudaGetSymbolAddress((void**)&pA,  g_bufA);
    cudaGetSymbolAddress((void**)&pH,  g_H16);
    cudaGetSymbolAddress((void**)&pBf, g_Bf16);
    __half* pAh = (__half*)pA;                       // alias g_bufA
    __half* pAl = pAh + (size_t)NN * FD;

    cudaFuncSetAttribute(k_tgemm<512, 1, 0>, cudaFuncAttributeMaxDynamicSharedMemorySize, GEMM_SMEM);
    cudaFuncSetAttribute(k_tgemm<128, 0, 1>, cudaFuncAttributeMaxDynamicSharedMemorySize, GEMM_SMEM);

    const int T = 256;
    const int ab = (NN * 32 + T - 1) / T;      // agg blocks

    // init: zero counts + dtype detect + all weight fp16 (1 launch)
    k_init<<<384, T>>>((const int*)ei, W1, W2, Wm, Ws);

    // GEMM1 fused with edge scatter (tail absorption)
    k_tgemm<512, 1, 0><<<GB + EB, T, GEMM_SMEM>>>(x, nullptr, nullptr, pBf, pH, ei);
    k_dis<<<(NN + T - 1) / T, T>>>();
    k_agg<1, 1><<<ab, T>>>((const uint2*)pH, b1, nullptr, nullptr, nullptr, pAh, pAl);
    // layer 2
    k_tgemm<128, 0, 1><<<GB, T, GEMM_SMEM>>>(nullptr, pAh, pAl, pBf + 65536, pH, nullptr);
    k_agg<1, 0><<<ab, T>>>((const uint2*)pH, b2, nullptr, nullptr, nullptr, pAh, pAl);
    // heads
    k_tgemm<128, 0, 1><<<GB, T, GEMM_SMEM>>>(nullptr, pAh, pAl, pBf + 81920, pH, nullptr);
    k_agg<2, 0><<<ab, T>>>((const uint2*)pH, bm, bs, outM, outS, nullptr, nullptr);
}

// round 12
// speedup vs baseline: 1.4189x; 1.0576x over previous
#include <cuda_runtime.h>
#include <cuda_bf16.h>
#include <cuda_fp16.h>
#include <cstdint>

#define NN 50000
#define EE 800000
#define FD 128
#define ZD 64
#define CAP 128          // bucket capacity per node (Poisson(16); overflow ~1e-18)

static constexpr int GB = (NN + 127) / 128;          // 391 GEMM tiles
static constexpr int EB = (EE + 255) / 256;          // 3125 edge blocks

// ---------------- scratch (device globals; no allocation allowed) ----------
__device__ __align__(256) float  g_bufA[NN * FD];    // aliased: fp16 Ah | Al
__device__ __align__(256) __half g_H16[NN * FD];
__device__ __align__(256) __half g_Bf16[128 * 512 + 2 * 128 * 128];
__device__ __align__(256) int    g_src[NN * CAP];
__device__ __align__(256) uint2  g_sw[NN * CAP];     // packed {src, weight}
__device__ int   g_cnt[NN];
__device__ float g_dis[NN];
__device__ int   g_is64;

// ---------------- PTX helpers ----------------------------------------------
__device__ __forceinline__ uint32_t smem_u32(const void* p) {
    uint32_t a;
    asm("{ .reg .u64 t; cvta.to.shared.u64 t, %1; cvt.u32.u64 %0, t; }"
        : "=r"(a) : "l"(p));
    return a;
}

__device__ __forceinline__ void cp_async16(uint32_t dst, const void* src) {
    asm volatile("cp.async.ca.shared.global [%0], [%1], 16;"
                 :: "r"(dst), "l"(src));
}
#define CP_COMMIT() asm volatile("cp.async.commit_group;")
#define CP_WAIT0()  asm volatile("cp.async.wait_group 0;" ::: "memory")

#define LDSM_X4(r0, r1, r2, r3, addr) \
    asm volatile("ldmatrix.sync.aligned.m8n8.x4.shared.b16 {%0,%1,%2,%3}, [%4];" \
        : "=r"(r0), "=r"(r1), "=r"(r2), "=r"(r3) : "r"(addr))

#define MMA_F16(d, a, b0, b1) \
    asm volatile("mma.sync.aligned.m16n8k16.row.col.f32.f16.f16.f32 " \
        "{%0,%1,%2,%3}, {%4,%5,%6,%7}, {%8,%9}, {%0,%1,%2,%3};" \
        : "+f"((d)[0]), "+f"((d)[1]), "+f"((d)[2]), "+f"((d)[3]) \
        : "r"((a)[0]), "r"((a)[1]), "r"((a)[2]), "r"((a)[3]), "r"(b0), "r"(b1))

// ---------------- preprocessing --------------------------------------------
__device__ __forceinline__ int edge_at(const void* eiv, long idx) {
    if (g_is64) return (int)((const long long*)eiv)[idx];
    return ((const int*)eiv)[idx];
}

// zero counts + detect dtype + weights -> fp16 [N=128][K]
__global__ void k_init(const int* __restrict__ ei32,
                       const float* __restrict__ W1, const float* __restrict__ W2,
                       const float* __restrict__ Wm, const float* __restrict__ Ws) {
    int i = blockIdx.x * blockDim.x + threadIdx.x;    // 384*256 = 98304
    if (i < NN) g_cnt[i] = 0;
    if (blockIdx.x == 0 && threadIdx.x < 32) {
        int v = ei32[2 * threadIdx.x + 1];
        unsigned m = __ballot_sync(0xffffffffu, v != 0);
        if (threadIdx.x == 0) g_is64 = (m == 0) ? 1 : 0;
    }
    float v;
    if (i < 65536) {
        int n = i >> 9, k = i & 511;
        v = W1[k * 128 + n];
    } else if (i < 81920) {
        int idx = i - 65536;
        int n = idx >> 7, k = idx & 127;
        v = W2[k * 128 + n];
    } else {
        int idx = i - 81920;
        int n = idx >> 7, k = idx & 127;
        v = (n < 64) ? Wm[k * 64 + n] : Ws[k * 64 + (n - 64)];
    }
    g_Bf16[i] = __float2half_rn(v);
}

// dis = rsqrt(deg+1), after counts complete
__global__ void k_dis() {
    int i = blockIdx.x * blockDim.x + threadIdx.x;
    if (i < NN) g_dis[i] = rsqrtf((float)(g_cnt[i] + 1));
}

// ---------------- fp16 tensor-core GEMM, fp16 output -----------------------
// 128x128 CTA tile, 8 warps of 32x64. FUSE: blocks >= GB run edge scatter.
// ASPLIT: A = Ah+Al split-2 fp16 (err ~2^-21); else single fp16 A.
// APRE: A pre-split fp16 in global (from k_agg) -> cp.async path.
static constexpr int ROWB   = 80;                 // padded 32-elem fp16 row
static constexpr int AHALF  = 128 * ROWB;         // 10240

template <int K, int FUSE, int APRE, int ASPLIT>
__global__ __launch_bounds__(256, 2) void k_tgemm(
    const float* __restrict__ A,
    const __half* __restrict__ Ah, const __half* __restrict__ Al,
    const __half* __restrict__ Bf,
    __half* __restrict__ C, const void* __restrict__ eiv)
{
    if (FUSE && blockIdx.x >= GB) {                 // edge-scatter role
        int e = (blockIdx.x - GB) * 256 + threadIdx.x;
        if (e < EE) {
            int s = edge_at(eiv, e);
            int d = edge_at(eiv, (long)EE + e);
            int pos = atomicAdd(&g_cnt[d], 1);
            if (pos < CAP) g_src[(d << 7) + pos] = s;
        }
        return;
    }

    extern __shared__ __align__(256) char smem[];
    constexpr int NA = ASPLIT ? 2 : 1;
    constexpr int STAGE = (NA + 1) * AHALF;        // A(h[,l]) | B
    constexpr int NCH = K / 32;
    const int tid  = threadIdx.x;
    const int wid  = tid >> 5;
    const int lane = tid & 31;
    const int warp_m = wid & 3;
    const int warp_n = wid >> 2;
    const uint32_t sb = smem_u32(smem);
    const int rowBase = blockIdx.x * 128;

    const uint32_t a_off = (uint32_t)(((lane & 7) + ((lane >> 3) & 1) * 8) * ROWB
                                      + ((lane >> 4) & 1) * 16);
    const uint32_t b_off = (uint32_t)((((lane >> 4) & 1) * 8 + (lane & 7)) * ROWB
                                      + ((lane >> 3) & 1) * 16);

    float acc[2][8][4];
#pragma unroll
    for (int t = 0; t < 2; t++)
#pragma unroll
        for (int j = 0; j < 8; j++)
#pragma unroll
            for (int v = 0; v < 4; v++) acc[t][j][v] = 0.f;

    const int ar = tid >> 1;          // 128 rows, 2 thr/row
    const int aq = (tid & 1) * 4;     // fp32 A path: quad base (4 iters)
    const int br = tid >> 1;
    const int bq = (tid & 1) << 1;    // 16B chunk base (2 iters)

    auto cpB = [&](int c, int s) {
        uint32_t stb = sb + s * STAGE;
#pragma unroll
        for (int it = 0; it < 2; it++) {
            int q = bq + it;
            uint32_t off = (uint32_t)(br * ROWB + q * 16);
            size_t idx = (size_t)br * K + c * 32 + q * 8;
            cp_async16(stb + NA * AHALF + off, Bf + idx);
        }
        CP_COMMIT();
    };

    auto cpA = [&](int c, int s) {    // APRE path (split-2 fp16 in global)
        uint32_t stb = sb + s * STAGE;
        int row = rowBase + br;
        if (row < NN) {
#pragma unroll
            for (int it = 0; it < 2; it++) {
                int q = bq + it;
                uint32_t off = (uint32_t)(br * ROWB + q * 16);
                size_t idx = (size_t)row * K + c * 32 + q * 8;
                cp_async16(stb + off, Ah + idx);
                cp_async16(stb + AHALF + off, Al + idx);
            }
        }
        CP_COMMIT();
    };

    auto ldgA = [&](int c, float4* pa) {
#pragma unroll
        for (int it = 0; it < 4; it++) {
            int q = aq + it;
            int row = rowBase + ar;
            float4 v = make_float4(0.f, 0.f, 0.f, 0.f);
            if (row < NN)
                v = *reinterpret_cast<const float4*>(&A[(size_t)row * K + c * 32 + q * 4]);
            pa[it] = v;
        }
    };

    auto stsA = [&](int s, const float4* pa) {   // fp32 -> fp16 (split iff ASPLIT)
        char* st = smem + s * STAGE;
#pragma unroll
        for (int it = 0; it < 4; it++) {
            int q = aq + it;
            float4 v = pa[it];
            __half2 h01 = __floats2half2_rn(v.x, v.y);
            __half2 h23 = __floats2half2_rn(v.z, v.w);
            uint32_t off = (uint32_t)(ar * ROWB + q * 8);
            *reinterpret_cast<__half2*>(st + off)     = h01;
            *reinterpret_cast<__half2*>(st + off + 4) = h23;
            if (ASPLIT) {
                float2 hf0 = __half22float2(h01);
                float2 hf1 = __half22float2(h23);
                __half2 l01 = __floats2half2_rn(v.x - hf0.x, v.y - hf0.y);
                __half2 l23 = __floats2half2_rn(v.z - hf1.x, v.w - hf1.y);
                *reinterpret_cast<__half2*>(st + AHALF + off)     = l01;
                *reinterpret_cast<__half2*>(st + AHALF + off + 4) = l23;
            }
        }
    };

    {   // prologue: chunk 0 -> stage 0
        if (APRE) {
            cpA(0, 0);
            cpB(0, 0);
        } else {
            float4 pa[4];
            ldgA(0, pa);
            cpB(0, 0);
            stsA(0, pa);
        }
        CP_WAIT0();
    }
    __syncthreads();

    for (int c = 0; c < NCH; c++) {
        const int s = c & 1;
        float4 pa[4];
        if (c + 1 < NCH) {
            if (APRE) {
                cpA(c + 1, s ^ 1);
                cpB(c + 1, s ^ 1);
            } else {
                ldgA(c + 1, pa);
                cpB(c + 1, s ^ 1);
            }
        }

        const uint32_t aBaseH = sb + s * STAGE + (uint32_t)(warp_m * 32) * ROWB;
        const uint32_t bBaseH = sb + s * STAGE + NA * AHALF + (uint32_t)(warp_n * 64) * ROWB;

#pragma unroll
        for (int sk = 0; sk < 2; sk++) {
            uint32_t ah[2][4], al[2][4];
#pragma unroll
            for (int t = 0; t < 2; t++) {
                uint32_t ad = aBaseH + (uint32_t)(t * 16 * ROWB + sk * 32) + a_off;
                LDSM_X4(ah[t][0], ah[t][1], ah[t][2], ah[t][3], ad);
                if (ASPLIT) LDSM_X4(al[t][0], al[t][1], al[t][2], al[t][3], ad + AHALF);
            }
#pragma unroll
            for (int jp = 0; jp < 4; jp++) {
                uint32_t bf[4];
                uint32_t bd = bBaseH + (uint32_t)(jp * 16 * ROWB + sk * 32) + b_off;
                LDSM_X4(bf[0], bf[1], bf[2], bf[3], bd);
#pragma unroll
                for (int t = 0; t < 2; t++)
#pragma unroll
                    for (int jj = 0; jj < 2; jj++) {
                        int j = jp * 2 + jj, o = jj * 2;
                        MMA_F16(acc[t][j], ah[t], bf[o], bf[o + 1]);
                        if (ASPLIT) MMA_F16(acc[t][j], al[t], bf[o], bf[o + 1]);
                    }
            }
        }

        if (c + 1 < NCH) {
            if (!APRE) stsA(s ^ 1, pa);
            CP_WAIT0();
        }
        __syncthreads();
    }

    // epilogue: fp16 stores
    const int r0 = rowBase + warp_m * 32 + (lane >> 2);
    const int cb = (lane & 3) * 2;
#pragma unroll
    for (int t = 0; t < 2; t++) {
#pragma unroll
        for (int j = 0; j < 8; j++) {
            int col = warp_n * 64 + j * 8 + cb;
            int ra = r0 + t * 16;
            int rb = ra + 8;
            if (ra < NN)
                *reinterpret_cast<__half2*>(&C[(size_t)ra * 128 + col]) =
                    __floats2half2_rn(acc[t][j][0], acc[t][j][1]);
            if (rb < NN)
                *reinterpret_cast<__half2*>(&C[(size_t)rb * 128 + col]) =
                    __floats2half2_rn(acc[t][j][2], acc[t][j][3]);
        }
    }
}

// ---------------- aggregation (fp16 gathers, fp32 accumulate) --------------
// MODE 1: h = relu(sum + biasA) -> fp16 hi/lo split arrays (next GEMM A input)
// MODE 2: cols 0-63 -> OA + biasA, cols 64-127 -> OB + biasB (fp32 [node][64])
// WST 1: compute w = dis[s]*dis[d], store packed {src,w}; WST 0: load packed.
template <int MODE, int WST>
__global__ __launch_bounds__(256) void k_agg(
    const uint2* __restrict__ G,   // fp16 table: [node][32] x 8B
    const float* __restrict__ biasA, const float* __restrict__ biasB,
    float* __restrict__ OA, float* __restrict__ OB,
    __half* __restrict__ Hh, __half* __restrict__ Hl)
{
    int node = (blockIdx.x * blockDim.x + threadIdx.x) >> 5;
    int lane = threadIdx.x & 31;
    if (node >= NN) return;
    int n = g_cnt[node];
    n = (n < CAP) ? n : CAP;
    const int base = node << 7;
    float dd = g_dis[node];
    float w0 = dd * dd;
    uint2 r = G[(size_t)node * 32 + lane];
    float2 p0 = __half22float2(*reinterpret_cast<__half2*>(&r.x));
    float2 p1 = __half22float2(*reinterpret_cast<__half2*>(&r.y));
    float4 acc = make_float4(w0 * p0.x, w0 * p0.y, w0 * p1.x, w0 * p1.y);
#pragma unroll 8
    for (int j = 0; j < n; j++) {
        int s; float w;
        if (WST) {
            s = g_src[base + j];
            w = g_dis[s] * dd;
            if (lane == 0) {
                uint2 sw;
                sw.x = (unsigned)s;
                sw.y = __float_as_uint(w);
                g_sw[base + j] = sw;
            }
        } else {
            uint2 sw = g_sw[base + j];       // one 8B broadcast load
            s = (int)sw.x;
            w = __uint_as_float(sw.y);
        }
        uint2 m = G[(size_t)s * 32 + lane];
        float2 q0 = __half22float2(*reinterpret_cast<__half2*>(&m.x));
        float2 q1 = __half22float2(*reinterpret_cast<__half2*>(&m.y));
        acc.x = fmaf(w, q0.x, acc.x);
        acc.y = fmaf(w, q0.y, acc.y);
        acc.z = fmaf(w, q1.x, acc.z);
        acc.w = fmaf(w, q1.y, acc.w);
    }
    if (MODE == 1) {
        float4 b = reinterpret_cast<const float4*>(biasA)[lane];
        acc.x = fmaxf(acc.x + b.x, 0.f);
        acc.y = fmaxf(acc.y + b.y, 0.f);
        acc.z = fmaxf(acc.z + b.z, 0.f);
        acc.w = fmaxf(acc.w + b.w, 0.f);
        // split to fp16 hi/lo for next GEMM's cp.async A path
        __half2 h01 = __floats2half2_rn(acc.x, acc.y);
        __half2 h23 = __floats2half2_rn(acc.z, acc.w);
        float2 hf0 = __half22float2(h01);
        float2 hf1 = __half22float2(h23);
        __half2 l01 = __floats2half2_rn(acc.x - hf0.x, acc.y - hf0.y);
        __half2 l23 = __floats2half2_rn(acc.z - hf1.x, acc.w - hf1.y);
        size_t o = (size_t)node * 128 + lane * 4;
        uint2 hv, lv;
        hv.x = *reinterpret_cast<uint32_t*>(&h01);
        hv.y = *reinterpret_cast<uint32_t*>(&h23);
        lv.x = *reinterpret_cast<uint32_t*>(&l01);
        lv.y = *reinterpret_cast<uint32_t*>(&l23);
        *reinterpret_cast<uint2*>(Hh + o) = hv;
        *reinterpret_cast<uint2*>(Hl + o) = lv;
    } else {
        if (lane < 16) {
            float4 b = reinterpret_cast<const float4*>(biasA)[lane];
            acc.x += b.x; acc.y += b.y; acc.z += b.z; acc.w += b.w;
            reinterpret_cast<float4*>(OA)[(size_t)node * 16 + lane] = acc;
        } else {
            float4 b = reinterpret_cast<const float4*>(biasB)[lane - 16];
            acc.x += b.x; acc.y += b.y; acc.z += b.z; acc.w += b.w;
            reinterpret_cast<float4*>(OB)[(size_t)node * 16 + (lane - 16)] = acc;
        }
    }
}

// ---------------- launch ----------------------------------------------------
extern "C" void kernel_launch(void* const* d_in, const int* in_sizes, int n_in,
                              void* d_out, int out_size) {
    const float* x  = (const float*)d_in[0];
    const void*  ei = d_in[1];
    const float* W1 = (const float*)d_in[2];
    const float* b1 = (const float*)d_in[3];
    const float* W2 = (const float*)d_in[4];
    const float* b2 = (const float*)d_in[5];
    const float* Wm = (const float*)d_in[6];
    const float* bm = (const float*)d_in[7];
    const float* Ws = (const float*)d_in[8];
    const float* bs = (const float*)d_in[9];
    float* outM = (float*)d_out;
    float* outS = outM + (long)NN * ZD;

    float*  pA  = nullptr;
    __half* pH  = nullptr;
    __half* pBf = nullptr;
    cudaGetSymbolAddress((void**)&pA,  g_bufA);
    cudaGetSymbolAddress((void**)&pH,  g_H16);
    cudaGetSymbolAddress((void**)&pBf, g_Bf16);
    __half* pAh = (__half*)pA;                       // alias g_bufA
    __half* pAl = pAh + (size_t)NN * FD;

    const int SM1 = 2 * (2 * AHALF);                 // GEMM1: A | B, 2 stages
    const int SM2 = 2 * (3 * AHALF);                 // GEMM2/3: Ah|Al|B, 2 stages
    cudaFuncSetAttribute(k_tgemm<512, 1, 0, 0>, cudaFuncAttributeMaxDynamicSharedMemorySize, SM1);
    cudaFuncSetAttribute(k_tgemm<128, 0, 1, 1>, cudaFuncAttributeMaxDynamicSharedMemorySize, SM2);

    const int T = 256;
    const int ab = (NN * 32 + T - 1) / T;      // agg blocks

    // init: zero counts + dtype detect + all weight fp16 (1 launch)
    k_init<<<384, T>>>((const int*)ei, W1, W2, Wm, Ws);

    // GEMM1 (single-fp16 A) fused with edge scatter (tail absorption)
    k_tgemm<512, 1, 0, 0><<<GB + EB, T, SM1>>>(x, nullptr, nullptr, pBf, pH, ei);
    k_dis<<<(NN + T - 1) / T, T>>>();
    k_agg<1, 1><<<ab, T>>>((const uint2*)pH, b1, nullptr, nullptr, nullptr, pAh, pAl);
    // layer 2 (A split-2)
    k_tgemm<128, 0, 1, 1><<<GB, T, SM2>>>(nullptr, pAh, pAl, pBf + 65536, pH, nullptr);
    k_agg<1, 0><<<ab, T>>>((const uint2*)pH, b2, nullptr, nullptr, nullptr, pAh, pAl);
    // heads (A split-2)
    k_tgemm<128, 0, 1, 1><<<GB, T, SM2>>>(nullptr, pAh, pAl, pBf + 81920, pH, nullptr);
    k_agg<2, 0><<<ab, T>>>((const uint2*)pH, bm, bs, outM, outS, nullptr, nullptr);
}

// round 13
// speedup vs baseline: 1.5100x; 1.0642x over previous
#include <cuda_runtime.h>
#include <cuda_bf16.h>
#include <cuda_fp16.h>
#include <cstdint>

#define NN 50000
#define EE 800000
#define FD 128
#define ZD 64
#define CAP 128          // bucket capacity per node (Poisson(16); overflow ~1e-18)

static constexpr int GB = (NN + 127) / 128;          // 391 GEMM tiles
static constexpr int EB = (EE + 255) / 256;          // 3125 edge blocks

// ---------------- scratch (device globals; no allocation allowed) ----------
__device__ __align__(256) float  g_bufA[NN * FD];    // aliased: fp16 A rows
__device__ __align__(256) __half g_H16[NN * FD];
__device__ __align__(256) __half g_Bf16[128 * 512 + 2 * 128 * 128];
__device__ __align__(256) int    g_src[NN * CAP];
__device__ __align__(256) uint2  g_sw[NN * CAP];     // packed {src, weight}
__device__ int   g_cnt[NN];
__device__ float g_dis[NN];
__device__ int   g_is64;

// ---------------- PTX helpers ----------------------------------------------
__device__ __forceinline__ uint32_t smem_u32(const void* p) {
    uint32_t a;
    asm("{ .reg .u64 t; cvta.to.shared.u64 t, %1; cvt.u32.u64 %0, t; }"
        : "=r"(a) : "l"(p));
    return a;
}

__device__ __forceinline__ void cp_async16(uint32_t dst, const void* src) {
    asm volatile("cp.async.ca.shared.global [%0], [%1], 16;"
                 :: "r"(dst), "l"(src));
}
#define CP_COMMIT() asm volatile("cp.async.commit_group;")
#define CP_WAIT0()  asm volatile("cp.async.wait_group 0;" ::: "memory")

#define LDSM_X4(r0, r1, r2, r3, addr) \
    asm volatile("ldmatrix.sync.aligned.m8n8.x4.shared.b16 {%0,%1,%2,%3}, [%4];" \
        : "=r"(r0), "=r"(r1), "=r"(r2), "=r"(r3) : "r"(addr))

#define MMA_F16(d, a, b0, b1) \
    asm volatile("mma.sync.aligned.m16n8k16.row.col.f32.f16.f16.f32 " \
        "{%0,%1,%2,%3}, {%4,%5,%6,%7}, {%8,%9}, {%0,%1,%2,%3};" \
        : "+f"((d)[0]), "+f"((d)[1]), "+f"((d)[2]), "+f"((d)[3]) \
        : "r"((a)[0]), "r"((a)[1]), "r"((a)[2]), "r"((a)[3]), "r"(b0), "r"(b1))

// ---------------- preprocessing --------------------------------------------
__device__ __forceinline__ int edge_at(const void* eiv, long idx) {
    if (g_is64) return (int)((const long long*)eiv)[idx];
    return ((const int*)eiv)[idx];
}

// zero counts + detect dtype + weights -> fp16 [N=128][K]
__global__ void k_init(const int* __restrict__ ei32,
                       const float* __restrict__ W1, const float* __restrict__ W2,
                       const float* __restrict__ Wm, const float* __restrict__ Ws) {
    int i = blockIdx.x * blockDim.x + threadIdx.x;    // 384*256 = 98304
    if (i < NN) g_cnt[i] = 0;
    if (blockIdx.x == 0 && threadIdx.x < 32) {
        int v = ei32[2 * threadIdx.x + 1];
        unsigned m = __ballot_sync(0xffffffffu, v != 0);
        if (threadIdx.x == 0) g_is64 = (m == 0) ? 1 : 0;
    }
    float v;
    if (i < 65536) {
        int n = i >> 9, k = i & 511;
        v = W1[k * 128 + n];
    } else if (i < 81920) {
        int idx = i - 65536;
        int n = idx >> 7, k = idx & 127;
        v = W2[k * 128 + n];
    } else {
        int idx = i - 81920;
        int n = idx >> 7, k = idx & 127;
        v = (n < 64) ? Wm[k * 64 + n] : Ws[k * 64 + (n - 64)];
    }
    g_Bf16[i] = __float2half_rn(v);
}

// dis = rsqrt(deg+1), after counts complete
__global__ void k_dis() {
    int i = blockIdx.x * blockDim.x + threadIdx.x;
    if (i < NN) g_dis[i] = rsqrtf((float)(g_cnt[i] + 1));
}

// ---------------- fp16 tensor-core GEMM, fp16 output -----------------------
// 128x128 CTA tile, 8 warps of 32x64. FUSE: blocks >= GB run edge scatter.
// APRE: A is fp16 rows in global (from k_agg) -> cp.async path.
static constexpr int ROWB   = 80;                 // padded 32-elem fp16 row
static constexpr int AHALF  = 128 * ROWB;         // 10240
static constexpr int STAGE  = 2 * AHALF;          // A | B
static constexpr int GEMM_SMEM = 2 * STAGE;       // 40960

template <int K, int FUSE, int APRE>
__global__ __launch_bounds__(256, 2) void k_tgemm(
    const float* __restrict__ A,
    const __half* __restrict__ Ah,
    const __half* __restrict__ Bf,
    __half* __restrict__ C, const void* __restrict__ eiv)
{
    if (FUSE && blockIdx.x >= GB) {                 // edge-scatter role
        int e = (blockIdx.x - GB) * 256 + threadIdx.x;
        if (e < EE) {
            int s = edge_at(eiv, e);
            int d = edge_at(eiv, (long)EE + e);
            int pos = atomicAdd(&g_cnt[d], 1);
            if (pos < CAP) g_src[(d << 7) + pos] = s;
        }
        return;
    }

    extern __shared__ __align__(256) char smem[];
    constexpr int NCH = K / 32;
    const int tid  = threadIdx.x;
    const int wid  = tid >> 5;
    const int lane = tid & 31;
    const int warp_m = wid & 3;
    const int warp_n = wid >> 2;
    const uint32_t sb = smem_u32(smem);
    const int rowBase = blockIdx.x * 128;

    const uint32_t a_off = (uint32_t)(((lane & 7) + ((lane >> 3) & 1) * 8) * ROWB
                                      + ((lane >> 4) & 1) * 16);
    const uint32_t b_off = (uint32_t)((((lane >> 4) & 1) * 8 + (lane & 7)) * ROWB
                                      + ((lane >> 3) & 1) * 16);

    float acc[2][8][4];
#pragma unroll
    for (int t = 0; t < 2; t++)
#pragma unroll
        for (int j = 0; j < 8; j++)
#pragma unroll
            for (int v = 0; v < 4; v++) acc[t][j][v] = 0.f;

    const int ar = tid >> 1;          // 128 rows, 2 thr/row
    const int aq = (tid & 1) * 4;     // fp32 A path: quad base (4 iters)
    const int br = tid >> 1;
    const int bq = (tid & 1) << 1;    // 16B chunk base (2 iters)

    auto cpB = [&](int c, int s) {
        uint32_t stb = sb + s * STAGE;
#pragma unroll
        for (int it = 0; it < 2; it++) {
            int q = bq + it;
            uint32_t off = (uint32_t)(br * ROWB + q * 16);
            size_t idx = (size_t)br * K + c * 32 + q * 8;
            cp_async16(stb + AHALF + off, Bf + idx);
        }
        CP_COMMIT();
    };

    auto cpA = [&](int c, int s) {    // APRE path (fp16 rows in global)
        uint32_t stb = sb + s * STAGE;
        int row = rowBase + br;
        if (row < NN) {
#pragma unroll
            for (int it = 0; it < 2; it++) {
                int q = bq + it;
                uint32_t off = (uint32_t)(br * ROWB + q * 16);
                size_t idx = (size_t)row * K + c * 32 + q * 8;
                cp_async16(stb + off, Ah + idx);
            }
        }
        CP_COMMIT();
    };

    auto ldgA = [&](int c, float4* pa) {
#pragma unroll
        for (int it = 0; it < 4; it++) {
            int q = aq + it;
            int row = rowBase + ar;
            float4 v = make_float4(0.f, 0.f, 0.f, 0.f);
            if (row < NN)
                v = *reinterpret_cast<const float4*>(&A[(size_t)row * K + c * 32 + q * 4]);
            pa[it] = v;
        }
    };

    auto stsA = [&](int s, const float4* pa) {   // fp32 -> fp16
        char* st = smem + s * STAGE;
#pragma unroll
        for (int it = 0; it < 4; it++) {
            int q = aq + it;
            float4 v = pa[it];
            __half2 h01 = __floats2half2_rn(v.x, v.y);
            __half2 h23 = __floats2half2_rn(v.z, v.w);
            uint32_t off = (uint32_t)(ar * ROWB + q * 8);
            *reinterpret_cast<__half2*>(st + off)     = h01;
            *reinterpret_cast<__half2*>(st + off + 4) = h23;
        }
    };

    {   // prologue: chunk 0 -> stage 0
        if (APRE) {
            cpA(0, 0);
            cpB(0, 0);
        } else {
            float4 pa[4];
            ldgA(0, pa);
            cpB(0, 0);
            stsA(0, pa);
        }
        CP_WAIT0();
    }
    __syncthreads();

    for (int c = 0; c < NCH; c++) {
        const int s = c & 1;
        float4 pa[4];
        if (c + 1 < NCH) {
            if (APRE) {
                cpA(c + 1, s ^ 1);
                cpB(c + 1, s ^ 1);
            } else {
                ldgA(c + 1, pa);
                cpB(c + 1, s ^ 1);
            }
        }

        const uint32_t aBaseH = sb + s * STAGE + (uint32_t)(warp_m * 32) * ROWB;
        const uint32_t bBaseH = sb + s * STAGE + AHALF + (uint32_t)(warp_n * 64) * ROWB;

#pragma unroll
        for (int sk = 0; sk < 2; sk++) {
            uint32_t ah[2][4];
#pragma unroll
            for (int t = 0; t < 2; t++) {
                uint32_t ad = aBaseH + (uint32_t)(t * 16 * ROWB + sk * 32) + a_off;
                LDSM_X4(ah[t][0], ah[t][1], ah[t][2], ah[t][3], ad);
            }
#pragma unroll
            for (int jp = 0; jp < 4; jp++) {
                uint32_t bf[4];
                uint32_t bd = bBaseH + (uint32_t)(jp * 16 * ROWB + sk * 32) + b_off;
                LDSM_X4(bf[0], bf[1], bf[2], bf[3], bd);
#pragma unroll
                for (int t = 0; t < 2; t++)
#pragma unroll
                    for (int jj = 0; jj < 2; jj++) {
                        int j = jp * 2 + jj, o = jj * 2;
                        MMA_F16(acc[t][j], ah[t], bf[o], bf[o + 1]);
                    }
            }
        }

        if (c + 1 < NCH) {
            if (!APRE) stsA(s ^ 1, pa);
            CP_WAIT0();
        }
        __syncthreads();
    }

    // epilogue: fp16 stores
    const int r0 = rowBase + warp_m * 32 + (lane >> 2);
    const int cb = (lane & 3) * 2;
#pragma unroll
    for (int t = 0; t < 2; t++) {
#pragma unroll
        for (int j = 0; j < 8; j++) {
            int col = warp_n * 64 + j * 8 + cb;
            int ra = r0 + t * 16;
            int rb = ra + 8;
            if (ra < NN)
                *reinterpret_cast<__half2*>(&C[(size_t)ra * 128 + col]) =
                    __floats2half2_rn(acc[t][j][0], acc[t][j][1]);
            if (rb < NN)
                *reinterpret_cast<__half2*>(&C[(size_t)rb * 128 + col]) =
                    __floats2half2_rn(acc[t][j][2], acc[t][j][3]);
        }
    }
}

// ---------------- aggregation: 2 edges/warp-iter (fp16 gathers, fp32 acc) --
// Warp = one node. Lanes 0-15 handle edge j (features fl*8..+8 via uint4),
// lanes 16-31 handle edge j+1; halves combined by shfl_xor(16) at the end.
// MODE 1: h = relu(sum + biasA) -> fp16 rows (next GEMM A input)
// MODE 2: cols 0-63 -> OA + biasA, cols 64-127 -> OB + biasB (fp32 [node][64])
// WST 1: compute w = dis[s]*dis[d], store packed {src,w}; WST 0: load packed.
template <int MODE, int WST>
__global__ __launch_bounds__(128) void k_agg(
    const uint4* __restrict__ G4,   // fp16 table rows: [node][16] x 16B
    const float* __restrict__ biasA, const float* __restrict__ biasB,
    float* __restrict__ OA, float* __restrict__ OB,
    __half* __restrict__ Hh)
{
    int node = (blockIdx.x * blockDim.x + threadIdx.x) >> 5;
    int lane = threadIdx.x & 31;
    if (node >= NN) return;
    int n = g_cnt[node];
    n = (n < CAP) ? n : CAP;
    const int base = node << 7;
    const int half = lane >> 4;
    const int fl   = lane & 15;
    float dd = g_dis[node];

    float acc[8];
    {   // self loop term (half 0 only; half 1 contributes 0)
        uint4 r = G4[(size_t)node * 16 + fl];
        const __half2* h = reinterpret_cast<const __half2*>(&r);
        float wself = half ? 0.f : dd * dd;
#pragma unroll
        for (int q = 0; q < 4; q++) {
            float2 f = __half22float2(h[q]);
            acc[q * 2]     = wself * f.x;
            acc[q * 2 + 1] = wself * f.y;
        }
    }

#pragma unroll 4
    for (int j = 0; j < n; j += 2) {
        int jj = j + half;
        bool valid = jj < n;
        int jc = valid ? jj : j;
        int s; float w;
        if (WST) {
            s = g_src[base + jc];
            w = g_dis[s] * dd;
            if (valid && fl == 0) {
                uint2 sw;
                sw.x = (unsigned)s;
                sw.y = __float_as_uint(w);
                g_sw[base + jc] = sw;
            }
        } else {
            uint2 sw = g_sw[base + jc];
            s = (int)sw.x;
            w = __uint_as_float(sw.y);
        }
        if (!valid) w = 0.f;
        uint4 m = G4[(size_t)s * 16 + fl];
        const __half2* h = reinterpret_cast<const __half2*>(&m);
#pragma unroll
        for (int q = 0; q < 4; q++) {
            float2 f = __half22float2(h[q]);
            acc[q * 2]     = fmaf(w, f.x, acc[q * 2]);
            acc[q * 2 + 1] = fmaf(w, f.y, acc[q * 2 + 1]);
        }
    }

    // combine halves
#pragma unroll
    for (int q = 0; q < 8; q++)
        acc[q] += __shfl_xor_sync(0xffffffffu, acc[q], 16);

    if (half == 0) {
        if (MODE == 1) {
            float4 b0 = reinterpret_cast<const float4*>(biasA)[fl * 2];
            float4 b1 = reinterpret_cast<const float4*>(biasA)[fl * 2 + 1];
            float r0 = fmaxf(acc[0] + b0.x, 0.f);
            float r1 = fmaxf(acc[1] + b0.y, 0.f);
            float r2 = fmaxf(acc[2] + b0.z, 0.f);
            float r3 = fmaxf(acc[3] + b0.w, 0.f);
            float r4 = fmaxf(acc[4] + b1.x, 0.f);
            float r5 = fmaxf(acc[5] + b1.y, 0.f);
            float r6 = fmaxf(acc[6] + b1.z, 0.f);
            float r7 = fmaxf(acc[7] + b1.w, 0.f);
            __half2 h0 = __floats2half2_rn(r0, r1);
            __half2 h1 = __floats2half2_rn(r2, r3);
            __half2 h2 = __floats2half2_rn(r4, r5);
            __half2 h3 = __floats2half2_rn(r6, r7);
            uint4 hv;
            hv.x = *reinterpret_cast<uint32_t*>(&h0);
            hv.y = *reinterpret_cast<uint32_t*>(&h1);
            hv.z = *reinterpret_cast<uint32_t*>(&h2);
            hv.w = *reinterpret_cast<uint32_t*>(&h3);
            *reinterpret_cast<uint4*>(Hh + (size_t)node * 128 + fl * 8) = hv;
        } else {
            float*       O    = (fl < 8) ? OA : OB;
            const float* bias = (fl < 8) ? biasA : biasB;
            int f = (fl & 7) * 8;
            float4 b0 = *reinterpret_cast<const float4*>(&bias[f]);
            float4 b1 = *reinterpret_cast<const float4*>(&bias[f + 4]);
            float4 v0 = make_float4(acc[0] + b0.x, acc[1] + b0.y,
                                    acc[2] + b0.z, acc[3] + b0.w);
            float4 v1 = make_float4(acc[4] + b1.x, acc[5] + b1.y,
                                    acc[6] + b1.z, acc[7] + b1.w);
            *reinterpret_cast<float4*>(&O[(size_t)node * 64 + f])     = v0;
            *reinterpret_cast<float4*>(&O[(size_t)node * 64 + f + 4]) = v1;
        }
    }
}

// ---------------- launch ----------------------------------------------------
extern "C" void kernel_launch(void* const* d_in, const int* in_sizes, int n_in,
                              void* d_out, int out_size) {
    const float* x  = (const float*)d_in[0];
    const void*  ei = d_in[1];
    const float* W1 = (const float*)d_in[2];
    const float* b1 = (const float*)d_in[3];
    const float* W2 = (const float*)d_in[4];
    const float* b2 = (const float*)d_in[5];
    const float* Wm = (const float*)d_in[6];
    const float* bm = (const float*)d_in[7];
    const float* Ws = (const float*)d_in[8];
    const float* bs = (const float*)d_in[9];
    float* outM = (float*)d_out;
    float* outS = outM + (long)NN * ZD;

    float*  pA  = nullptr;
    __half* pH  = nullptr;
    __half* pBf = nullptr;
    cudaGetSymbolAddress((void**)&pA,  g_bufA);
    cudaGetSymbolAddress((void**)&pH,  g_H16);
    cudaGetSymbolAddress((void**)&pBf, g_Bf16);
    __half* pAh = (__half*)pA;                       // alias g_bufA

    cudaFuncSetAttribute(k_tgemm<512, 1, 0>, cudaFuncAttributeMaxDynamicSharedMemorySize, GEMM_SMEM);
    cudaFuncSetAttribute(k_tgemm<128, 0, 1>, cudaFuncAttributeMaxDynamicSharedMemorySize, GEMM_SMEM);

    const int T = 256;
    const int ab = (NN * 32 + 127) / 128;      // agg blocks (128 thr)

    // init: zero counts + dtype detect + all weight fp16 (1 launch)
    k_init<<<384, T>>>((const int*)ei, W1, W2, Wm, Ws);

    // GEMM1 (single-fp16 A) fused with edge scatter (tail absorption)
    k_tgemm<512, 1, 0><<<GB + EB, T, GEMM_SMEM>>>(x, nullptr, pBf, pH, ei);
    k_dis<<<(NN + T - 1) / T, T>>>();
    k_agg<1, 1><<<ab, 128>>>((const uint4*)pH, b1, nullptr, nullptr, nullptr, pAh);
    // layer 2 (single-fp16 A via cp.async)
    k_tgemm<128, 0, 1><<<GB, T, GEMM_SMEM>>>(nullptr, pAh, pBf + 65536, pH, nullptr);
    k_agg<1, 0><<<ab, 128>>>((const uint4*)pH, b2, nullptr, nullptr, nullptr, pAh);
    // heads (single-fp16 A)
    k_tgemm<128, 0, 1><<<GB, T, GEMM_SMEM>>>(nullptr, pAh, pBf + 81920, pH, nullptr);
    k_agg<2, 0><<<ab, 128>>>((const uint4*)pH, bm, bs, outM, outS, nullptr);
}